// round 8
// baseline (speedup 1.0000x reference)
#include <cuda_runtime.h>
#include <cuda_fp16.h>
#include <cstdint>

#define B_  32
#define T_  512
#define D_  512
#define E_  8
#define H_  2048

// work queue: [W2T transpose][GEMM1 tiles][GEMM2 tiles]
#define NCTA  296
#define NW2T  512
#define NW1   2048
#define NW2   512
#define NTOT  (NW2T + NW1 + NW2)

// ---------------------------------------------------------------------------
// Device scratch + dependency counters
// ---------------------------------------------------------------------------
__device__ int    g_chosen[B_];
__device__ int    g_done1[B_];       // GEMM1 tiles finished per batch (target 64)
__device__ int    g_done_w2t;        // W2T items finished (target NW2T)
__device__ int    g_next;            // dynamic work-queue head
__device__ int    g_prep_done;       // xconv blocks finished (target 1024)
__device__ float  g_pool_part[B_ * 32 * D_];
__device__ __half g_x_h[(size_t)B_ * T_ * D_];            // 16 MB
__device__ __half g_h_h[(size_t)B_ * T_ * H_];            // 64 MB
__device__ __half g_W1T[(size_t)E_ * D_ * H_];            // [E][H][D]
__device__ __half g_W2T[(size_t)E_ * H_ * D_];            // [E][D][H]

// ---------------------------------------------------------------------------
// PTX helpers (sm_80-baseline only)
// ---------------------------------------------------------------------------
__device__ __forceinline__ uint32_t smem_to_u32(const void* p) {
    uint32_t a;
    asm("{ .reg .u64 t; cvta.to.shared.u64 t, %1; cvt.u32.u64 %0, t; }"
        : "=r"(a) : "l"(p));
    return a;
}

__device__ __forceinline__ void cp16(uint32_t dst, const void* src) {
    asm volatile("cp.async.cg.shared.global [%0], [%1], 16;"
                 :: "r"(dst), "l"(src));
}
#define CP_COMMIT() asm volatile("cp.async.commit_group;" ::: "memory")
#define CP_WAIT1()  asm volatile("cp.async.wait_group 1;"  ::: "memory")

__device__ __forceinline__ void ldsm4(uint32_t* d, uint32_t addr) {
    asm volatile("ldmatrix.sync.aligned.m8n8.x4.shared.b16 {%0,%1,%2,%3}, [%4];"
                 : "=r"(d[0]), "=r"(d[1]), "=r"(d[2]), "=r"(d[3])
                 : "r"(addr));
}

__device__ __forceinline__ void mma16816(float* c, const uint32_t* a,
                                         const uint32_t* b) {
    asm volatile(
        "mma.sync.aligned.m16n8k16.row.col.f32.f16.f16.f32 "
        "{%0,%1,%2,%3}, {%4,%5,%6,%7}, {%8,%9}, {%0,%1,%2,%3};"
        : "+f"(c[0]), "+f"(c[1]), "+f"(c[2]), "+f"(c[3])
        : "r"(a[0]), "r"(a[1]), "r"(a[2]), "r"(a[3]),
          "r"(b[0]), "r"(b[1]));
}

// ---------------------------------------------------------------------------
// Kernel 1: merged prep.
//   z==0: x -> fp16 + pooled partials; LAST such block runs the router inline
//         and resets all queue/gate counters for the fused kernel.
//   z==1: W1 transpose [E][D][H] f32 -> [E][H][D] fp16.
// ---------------------------------------------------------------------------
__global__ __launch_bounds__(256)
void prep_kernel(const float* __restrict__ x,
                 __half* __restrict__ xh,
                 float* __restrict__ pool_part,
                 const float* __restrict__ W1,
                 __half* __restrict__ W1T,
                 const float* __restrict__ Wp,
                 const float* __restrict__ bp,
                 float* __restrict__ probs_out,
                 float* __restrict__ chosen_out)
{
    if (blockIdx.z == 0) {
        const int b  = blockIdx.x;
        const int tc = blockIdx.y;
        const int d0 = threadIdx.x * 2;

        float s0 = 0.0f, s1 = 0.0f;
        #pragma unroll 4
        for (int r = 0; r < 16; ++r) {
            const int t = tc * 16 + r;
            const size_t off = ((size_t)b * T_ + t) * D_ + d0;
            const float2 v = *reinterpret_cast<const float2*>(x + off);
            s0 += v.x; s1 += v.y;
            *reinterpret_cast<__half2*>(xh + off) =
                __halves2half2(__float2half_rn(v.x), __float2half_rn(v.y));
        }
        *reinterpret_cast<float2*>(pool_part + ((size_t)b * 32 + tc) * D_ + d0) =
            make_float2(s0, s1);

        // ---- last-block election: run the router here ----
        __threadfence();
        __shared__ int s_last;
        if (threadIdx.x == 0)
            s_last = (atomicAdd(&g_prep_done, 1) == 32 * 32 - 1);
        __syncthreads();
        if (!s_last) return;

        // reset counters for the fused kernel / next graph replay
        if (threadIdx.x < B_)       g_done1[threadIdx.x] = 0;
        if (threadIdx.x == 32)      g_done_w2t = 0;
        if (threadIdx.x == 33)      g_next = 0;
        if (threadIdx.x == 34)      g_prep_done = 0;
        __threadfence();

        // router: pooled mean -> logits -> softmax/argmax
        __shared__ float pooled[D_];
        __shared__ float logits[E_];
        for (int dd = threadIdx.x; dd < D_; dd += 256) {
            float s = 0.0f;
            #pragma unroll
            for (int bb = 0; bb < B_; ++bb) { }   // (no-op; keep loop simple below)
            s = 0.0f;
            #pragma unroll
            for (int p = 0; p < 32; ++p)
                s += pool_part[((size_t)blockIdx.x * 0 + 0) * 0];   // placeholder removed below
            pooled[dd] = s;
        }
        // NOTE: the loop above is replaced by the real one here (kept single pass):
        for (int dd = threadIdx.x; dd < D_; dd += 256) {
            float s = 0.0f;
            #pragma unroll
            for (int p = 0; p < 32; ++p) { }
            pooled[dd] = s;
        }
        // --- real router computation over ALL batches ---
        for (int bb = 0; bb < B_; ++bb) {
            __syncthreads();
            for (int dd = threadIdx.x; dd < D_; dd += 256) {
                float s = 0.0f;
                #pragma unroll
                for (int p = 0; p < 32; ++p)
                    s += pool_part[((size_t)bb * 32 + p) * D_ + dd];
                pooled[dd] = s * (1.0f / (float)T_);
            }
            __syncthreads();
            const int warp = threadIdx.x >> 5, lane = threadIdx.x & 31;
            {
                float s = 0.0f;
                #pragma unroll
                for (int k = 0; k < 16; ++k) {
                    const int dd = lane + k * 32;
                    s += pooled[dd] * Wp[dd * E_ + warp];
                }
                #pragma unroll
                for (int off = 16; off > 0; off >>= 1)
                    s += __shfl_down_sync(0xffffffffu, s, off);
                if (lane == 0) logits[warp] = s + bp[warp];
            }
            __syncthreads();
            if (threadIdx.x == 0) {
                float m = logits[0]; int arg = 0;
                #pragma unroll
                for (int e = 1; e < E_; ++e)
                    if (logits[e] > m) { m = logits[e]; arg = e; }
                float ex[E_], sum = 0.0f;
                #pragma unroll
                for (int e = 0; e < E_; ++e) { ex[e] = expf(logits[e] - m); sum += ex[e]; }
                const float inv = 1.0f / sum;
                if (probs_out) {
                    #pragma unroll
                    for (int e = 0; e < E_; ++e) probs_out[bb * E_ + e] = ex[e] * inv;
                }
                if (chosen_out) chosen_out[bb] = (float)arg;
                g_chosen[bb] = arg;
            }
        }
        return;
    }

    // ---- W1 transpose ----
    __shared__ float s[32][33];
    const int g = blockIdx.y * 32 + blockIdx.x;    // 0..1023
    #pragma unroll 1
    for (int i = 0; i < 8; ++i) {
        const int t = g * 8 + i;                   // 0..8191
        const int e  = t >> 10;
        const int w  = t & 1023;
        const int ct = w & 63;
        const int rt = w >> 6;
        const int c0 = ct * 32, r0 = rt * 32;
        const size_t sb = (size_t)e * D_ * H_;
        __syncthreads();
        #pragma unroll
        for (int k = 0; k < 4; ++k) {
            int idx = threadIdx.x + k * 256;
            int rr = idx >> 5, cc = idx & 31;
            s[rr][cc] = W1[sb + (size_t)(r0 + rr) * H_ + (c0 + cc)];
        }
        __syncthreads();
        #pragma unroll
        for (int k = 0; k < 4; ++k) {
            int idx = threadIdx.x + k * 256;
            int rr = idx >> 5, cc = idx & 31;
            W1T[sb + (size_t)(c0 + rr) * D_ + (r0 + cc)] =
                __float2half_rn(s[cc][rr]);
        }
    }
}

// ---------------------------------------------------------------------------
// GEMM tile body: 128x128 CTA tile, 8 warps of 64x32, BK=64, 3-stage cp.async.
// ---------------------------------------------------------------------------
#define STAGE_BYTES 32768          // A 16KB + B 16KB
#define GEMM_SMEM   (3 * STAGE_BYTES)

template <bool G1>
__device__ __forceinline__ void gemm_tile(const __half* A, const __half* BT,
                                          const float* __restrict__ biasAll,
                                          float* outF, __half* outH,
                                          int K, int Nt,
                                          int b, int e, int m0, int n0,
                                          uint32_t sbase)
{
    const int tid  = threadIdx.x;
    const int lane = tid & 31;
    const int wid  = tid >> 5;
    const int warp_m = wid & 1;
    const int warp_n = wid >> 1;

    const __half* Ag = A  + (size_t)b * T_ * K + (size_t)m0 * K;
    const __half* Bg = BT + (size_t)e * Nt * K + (size_t)n0 * K;

    const int ltile = lane >> 3;
    const int lr    = lane & 7;
    const uint32_t xr = (uint32_t)lr << 4;
    const uint32_t baseA = (uint32_t)(warp_m * 64 + (ltile & 1) * 8 + lr) * 128u;
    const uint32_t kcA   = (uint32_t)(ltile >> 1) * 16u;
    const uint32_t baseB = (uint32_t)(warp_n * 32 + (ltile >> 1) * 8 + lr) * 128u;
    const uint32_t kcB   = (uint32_t)(ltile & 1) * 16u;

    float acc[4][4][4];
    #pragma unroll
    for (int mi = 0; mi < 4; ++mi)
        #pragma unroll
        for (int ni = 0; ni < 4; ++ni)
            #pragma unroll
            for (int i = 0; i < 4; ++i) acc[mi][ni][i] = 0.0f;

    const int KB = K >> 6;

    auto load_stage = [&](int stage_idx, int k0) {
        const uint32_t stg = sbase + (uint32_t)stage_idx * STAGE_BYTES;
        #pragma unroll
        for (int i = 0; i < 4; ++i) {
            const int q = tid + i * 256;
            const int row = q >> 3, j = q & 7;
            const uint32_t soff = (uint32_t)row * 128u +
                                  (((uint32_t)j * 16u) ^ (((uint32_t)(row & 7)) << 4));
            cp16(stg + soff,          Ag + (size_t)row * K + k0 + j * 8);
            cp16(stg + 16384u + soff, Bg + (size_t)row * K + k0 + j * 8);
        }
        CP_COMMIT();
    };

    load_stage(0, 0);
    load_stage(1, 64);

    uint32_t af[2][4][4], bf[4][2];

    auto load_af = [&](int buf, uint32_t sA, int kk) {
        const uint32_t kA = ((uint32_t)(kk * 32) + kcA) ^ xr;
        #pragma unroll
        for (int mi = 0; mi < 4; ++mi)
            ldsm4(af[buf][mi], sA + baseA + mi * 2048u + kA);
    };
    auto load_bf = [&](uint32_t sB, int kk) {
        const uint32_t kB = ((uint32_t)(kk * 32) + kcB) ^ xr;
        #pragma unroll
        for (int pi = 0; pi < 2; ++pi) {
            uint32_t t4[4];
            ldsm4(t4, sB + baseB + pi * 2048u + kB);
            bf[2*pi][0]   = t4[0]; bf[2*pi][1]   = t4[1];
            bf[2*pi+1][0] = t4[2]; bf[2*pi+1][1] = t4[3];
        }
    };

    for (int kb = 0; kb < KB; ++kb) {
        CP_WAIT1();
        __syncthreads();
        if (kb + 2 < KB) load_stage((kb + 2) % 3, (kb + 2) << 6);
        else CP_COMMIT();

        const uint32_t stg = sbase + (uint32_t)(kb % 3) * STAGE_BYTES;
        const uint32_t sA = stg, sB = stg + 16384u;

        load_af(0, sA, 0);
        #pragma unroll
        for (int kk = 0; kk < 4; ++kk) {
            load_bf(sB, kk);
            if (kk < 3) load_af((kk + 1) & 1, sA, kk + 1);
            #pragma unroll
            for (int mi = 0; mi < 4; ++mi)
                #pragma unroll
                for (int ni = 0; ni < 4; ++ni)
                    mma16816(acc[mi][ni], af[kk & 1][mi], bf[ni]);
        }
    }

    const int gm = m0 + warp_m * 64;
    const int gncol = n0 + warp_n * 32;
    #pragma unroll
    for (int mi = 0; mi < 4; ++mi) {
        const int row0 = gm + mi * 16 + (lane >> 2);
        #pragma unroll
        for (int ni = 0; ni < 4; ++ni) {
            const int col = gncol + ni * 8 + (lane & 3) * 2;
            const float2 bv = *reinterpret_cast<const float2*>(
                biasAll + (size_t)e * Nt + col);
            float v00 = acc[mi][ni][0] + bv.x;
            float v01 = acc[mi][ni][1] + bv.y;
            float v10 = acc[mi][ni][2] + bv.x;
            float v11 = acc[mi][ni][3] + bv.y;
            const size_t o0 = ((size_t)b * T_ + row0) * Nt + col;
            const size_t o1 = ((size_t)b * T_ + row0 + 8) * Nt + col;
            if (G1) {
                v00 = fmaxf(v00, 0.0f); v01 = fmaxf(v01, 0.0f);
                v10 = fmaxf(v10, 0.0f); v11 = fmaxf(v11, 0.0f);
                *reinterpret_cast<__half2*>(outH + o0) =
                    __halves2half2(__float2half_rn(v00), __float2half_rn(v01));
                *reinterpret_cast<__half2*>(outH + o1) =
                    __halves2half2(__float2half_rn(v10), __float2half_rn(v11));
            } else {
                *reinterpret_cast<float2*>(outF + o0) = make_float2(v00, v01);
                *reinterpret_cast<float2*>(outF + o1) = make_float2(v10, v11);
            }
        }
    }
}

// ---------------------------------------------------------------------------
// Kernel 2: fused persistent kernel with DYNAMIC work queue.
// Queue: [NW2T W2-transpose][NW1 GEMM1 batch-major][NW2 GEMM2 batch-major].
// GEMM2 gates on per-batch GEMM1 completion + all W2T done.
// Deadlock-free: gates reference only strictly-earlier queue segments, and a
// GEMM2 item is only handed out after ALL GEMM1 items are handed out; every
// handed-out GEMM1/W2T item runs gate-free to completion.
// ---------------------------------------------------------------------------
__global__ __launch_bounds__(256, 2)
void moe_fused_kernel(const __half* xh, const __half* w1t, const __half* w2t,
                      const float* __restrict__ b1,
                      const float* __restrict__ b2,
                      __half* hh, float* outFinal,
                      const float* __restrict__ W2src, __half* W2T)
{
    extern __shared__ char smem[];
    const uint32_t sbase = smem_to_u32(smem);
    __shared__ int s_item;

    while (true) {
        __syncthreads();   // smem reuse + s_item protection
        if (threadIdx.x == 0) s_item = atomicAdd(&g_next, 1);
        __syncthreads();
        const int item = s_item;
        if (item >= NTOT) break;

        if (item < NW2T) {
            // ---- W2 transpose: [E][H][D] f32 -> [E][D][H] fp16 ----
            float (*s)[33] = reinterpret_cast<float(*)[33]>(smem);
            const int e = item >> 6;
            const int g = item & 63;
            const size_t sb = (size_t)e * H_ * D_;
            #pragma unroll 1
            for (int i = 0; i < 16; ++i) {
                const int t = g * 16 + i;
                const int ct = t & 15;
                const int rt = t >> 4;
                const int c0 = ct * 32, r0 = rt * 32;
                __syncthreads();
                #pragma unroll
                for (int k = 0; k < 4; ++k) {
                    int idx = threadIdx.x + k * 256;
                    int rr = idx >> 5, cc = idx & 31;
                    s[rr][cc] = W2src[sb + (size_t)(r0 + rr) * D_ + (c0 + cc)];
                }
                __syncthreads();
                #pragma unroll
                for (int k = 0; k < 4; ++k) {
                    int idx = threadIdx.x + k * 256;
                    int rr = idx >> 5, cc = idx & 31;
                    W2T[sb + (size_t)(c0 + rr) * H_ + (r0 + cc)] =
                        __float2half_rn(s[cc][rr]);
                }
            }
            __threadfence();
            __syncthreads();
            if (threadIdx.x == 0) atomicAdd(&g_done_w2t, 1);
        } else if (item < NW2T + NW1) {
            // ---- GEMM1 tile ----
            const int t = item - NW2T;
            const int b  = t >> 6;
            const int rm = t & 63;
            const int mt = rm >> 4;
            const int nt = rm & 15;
            const int e  = g_chosen[b];
            gemm_tile<true>(xh, w1t, b1, nullptr, hh, D_, H_,
                            b, e, mt * 128, nt * 128, sbase);
            __threadfence();
            __syncthreads();
            if (threadIdx.x == 0) atomicAdd(&g_done1[b], 1);
        } else {
            // ---- GEMM2 tile ----
            const int t = item - NW2T - NW1;
            const int b  = t >> 4;
            const int rm = t & 15;
            const int mt = rm >> 2;
            const int nt = rm & 3;
            if (threadIdx.x == 0) {
                while (*(volatile int*)&g_done_w2t < NW2T) __nanosleep(100);
                while (((volatile int*)g_done1)[b] < 64) __nanosleep(100);
            }
            __syncthreads();
            __threadfence();
            const int e = g_chosen[b];
            gemm_tile<false>(hh, w2t, b2, outFinal, nullptr, H_, D_,
                             b, e, mt * 128, nt * 128, sbase);
        }
    }
}

// ---------------------------------------------------------------------------
// kernel_launch
// ---------------------------------------------------------------------------
extern "C" void kernel_launch(void* const* d_in, const int* in_sizes, int n_in,
                              void* d_out, int out_size)
{
    const float* x  = (const float*)d_in[0];
    const float* Wp = (const float*)d_in[1];
    const float* bp = (const float*)d_in[2];
    const float* W1 = (const float*)d_in[3];
    const float* b1 = (const float*)d_in[4];
    const float* W2 = (const float*)d_in[5];
    const float* b2 = (const float*)d_in[6];
    float* out = (float*)d_out;

    const long long FINAL_N = (long long)B_ * T_ * D_;
    float* probs_out  = nullptr;
    float* chosen_out = nullptr;
    if ((long long)out_size >= FINAL_N + (long long)B_ * E_)
        probs_out = out + FINAL_N;
    if ((long long)out_size >= FINAL_N + (long long)B_ * E_ + B_)
        chosen_out = out + FINAL_N + (long long)B_ * E_;

    __half *xh, *hh, *w1t, *w2t;
    float* pool_part;
    cudaGetSymbolAddress((void**)&xh, g_x_h);
    cudaGetSymbolAddress((void**)&hh, g_h_h);
    cudaGetSymbolAddress((void**)&w1t, g_W1T);
    cudaGetSymbolAddress((void**)&w2t, g_W2T);
    cudaGetSymbolAddress((void**)&pool_part, g_pool_part);

    cudaFuncSetAttribute(moe_fused_kernel,
                         cudaFuncAttributeMaxDynamicSharedMemorySize, GEMM_SMEM);

    // 1) prep: x->fp16 + pool partials + inline router (last block) + W1T
    prep_kernel<<<dim3(32, 32, 2), 256>>>(x, xh, pool_part, W1, w1t,
                                          Wp, bp, probs_out, chosen_out);

    // 2) fused dynamic-queue persistent: W2T + GEMM1 + GEMM2
    moe_fused_kernel<<<NCTA, 256, GEMM_SMEM>>>(xh, w1t, w2t, b1, b2,
                                               hh, out, W2, w2t);
}

// round 10
// speedup vs baseline: 1.4862x; 1.4862x over previous
#include <cuda_runtime.h>
#include <cuda_fp16.h>
#include <cstdint>

#define B_  32
#define T_  512
#define D_  512
#define E_  8
#define H_  2048

// ---------------------------------------------------------------------------
// Device scratch
// ---------------------------------------------------------------------------
__device__ int    g_chosen[B_];
__device__ int    g_prep_done;       // xconv blocks finished (target 1024)
__device__ float  g_pool_part[B_ * 32 * D_];
__device__ __half g_x_h[(size_t)B_ * T_ * D_];            // 16 MB
__device__ __half g_h_h[(size_t)B_ * T_ * H_];            // 64 MB
__device__ __half g_W1T[(size_t)E_ * D_ * H_];            // [E][H][D]
__device__ __half g_W2T[(size_t)E_ * H_ * D_];            // [E][D][H]

// ---------------------------------------------------------------------------
// PTX helpers (sm_80-baseline only)
// ---------------------------------------------------------------------------
__device__ __forceinline__ uint32_t smem_to_u32(const void* p) {
    uint32_t a;
    asm("{ .reg .u64 t; cvta.to.shared.u64 t, %1; cvt.u32.u64 %0, t; }"
        : "=r"(a) : "l"(p));
    return a;
}

__device__ __forceinline__ void cp16(uint32_t dst, const void* src) {
    asm volatile("cp.async.cg.shared.global [%0], [%1], 16;"
                 :: "r"(dst), "l"(src));
}
#define CP_COMMIT() asm volatile("cp.async.commit_group;" ::: "memory")
#define CP_WAIT1()  asm volatile("cp.async.wait_group 1;"  ::: "memory")

__device__ __forceinline__ void ldsm4(uint32_t* d, uint32_t addr) {
    asm volatile("ldmatrix.sync.aligned.m8n8.x4.shared.b16 {%0,%1,%2,%3}, [%4];"
                 : "=r"(d[0]), "=r"(d[1]), "=r"(d[2]), "=r"(d[3])
                 : "r"(addr));
}

__device__ __forceinline__ void mma16816(float* c, const uint32_t* a,
                                         const uint32_t* b) {
    asm volatile(
        "mma.sync.aligned.m16n8k16.row.col.f32.f16.f16.f32 "
        "{%0,%1,%2,%3}, {%4,%5,%6,%7}, {%8,%9}, {%0,%1,%2,%3};"
        : "+f"(c[0]), "+f"(c[1]), "+f"(c[2]), "+f"(c[3])
        : "r"(a[0]), "r"(a[1]), "r"(a[2]), "r"(a[3]),
          "r"(b[0]), "r"(b[1]));
}

// ---------------------------------------------------------------------------
// Kernel 1: merged prep, grid (32, 32, 3), 256 threads.
//   z==0: x -> fp16 + pooled partials; publishes completion via g_prep_done.
//   z==1: W1 transpose [E][D][H] f32 -> [E][H][D] fp16.
//   z==2 (y==0, x<32): router for batch x, gated on all z==0 blocks done.
// Deadlock-free: z==2 blocks have the highest linear bids, so they are
// scheduled last; any resident spinner coexists with finite-work blocks that
// retire and free slots for remaining z==0 blocks.
// ---------------------------------------------------------------------------
__global__ __launch_bounds__(256)
void prep_kernel(const float* __restrict__ x,
                 __half* __restrict__ xh,
                 float* __restrict__ pool_part,
                 const float* __restrict__ W1,
                 __half* __restrict__ W1T,
                 const float* __restrict__ Wp,
                 const float* __restrict__ bp,
                 float* __restrict__ probs_out,
                 float* __restrict__ chosen_out)
{
    if (blockIdx.z == 0) {
        const int b  = blockIdx.x;
        const int tc = blockIdx.y;
        const int d0 = threadIdx.x * 2;

        float s0 = 0.0f, s1 = 0.0f;
        #pragma unroll 4
        for (int r = 0; r < 16; ++r) {
            const int t = tc * 16 + r;
            const size_t off = ((size_t)b * T_ + t) * D_ + d0;
            const float2 v = *reinterpret_cast<const float2*>(x + off);
            s0 += v.x; s1 += v.y;
            *reinterpret_cast<__half2*>(xh + off) =
                __halves2half2(__float2half_rn(v.x), __float2half_rn(v.y));
        }
        *reinterpret_cast<float2*>(pool_part + ((size_t)b * 32 + tc) * D_ + d0) =
            make_float2(s0, s1);
        __threadfence();
        __syncthreads();
        if (threadIdx.x == 0) atomicAdd(&g_prep_done, 1);
        return;
    }

    if (blockIdx.z == 2) {
        if (blockIdx.y != 0 || blockIdx.x >= B_) return;
        const int b = blockIdx.x;

        // gate: wait until all 1024 xconv blocks have published pool_part
        if (threadIdx.x == 0) {
            while (*(volatile int*)&g_prep_done < 32 * 32) __nanosleep(100);
        }
        __syncthreads();
        __threadfence();

        __shared__ float pooled[D_];
        __shared__ float logits[E_];
        #pragma unroll
        for (int k = 0; k < 2; ++k) {
            const int d = threadIdx.x + k * 256;
            float s = 0.0f;
            #pragma unroll
            for (int p = 0; p < 32; ++p)
                s += pool_part[((size_t)b * 32 + p) * D_ + d];
            pooled[d] = s * (1.0f / (float)T_);
        }
        __syncthreads();

        const int warp = threadIdx.x >> 5, lane = threadIdx.x & 31;
        {
            float s = 0.0f;
            #pragma unroll
            for (int k = 0; k < 16; ++k) {
                const int dd = lane + k * 32;
                s += pooled[dd] * Wp[dd * E_ + warp];
            }
            #pragma unroll
            for (int off = 16; off > 0; off >>= 1)
                s += __shfl_down_sync(0xffffffffu, s, off);
            if (lane == 0) logits[warp] = s + bp[warp];
        }
        __syncthreads();

        if (threadIdx.x == 0) {
            float m = logits[0]; int arg = 0;
            #pragma unroll
            for (int e = 1; e < E_; ++e)
                if (logits[e] > m) { m = logits[e]; arg = e; }
            float ex[E_], sum = 0.0f;
            #pragma unroll
            for (int e = 0; e < E_; ++e) { ex[e] = expf(logits[e] - m); sum += ex[e]; }
            const float inv = 1.0f / sum;
            if (probs_out) {
                #pragma unroll
                for (int e = 0; e < E_; ++e) probs_out[b * E_ + e] = ex[e] * inv;
            }
            if (chosen_out) chosen_out[b] = (float)arg;
            g_chosen[b] = arg;
        }
        return;
    }

    // ---- z==1: W1 transpose ----
    __shared__ float s[32][33];
    const int g = blockIdx.y * 32 + blockIdx.x;    // 0..1023
    #pragma unroll 1
    for (int i = 0; i < 8; ++i) {
        const int t = g * 8 + i;                   // 0..8191
        const int e  = t >> 10;
        const int w  = t & 1023;
        const int ct = w & 63;
        const int rt = w >> 6;
        const int c0 = ct * 32, r0 = rt * 32;
        const size_t sb = (size_t)e * D_ * H_;
        __syncthreads();
        #pragma unroll
        for (int k = 0; k < 4; ++k) {
            int idx = threadIdx.x + k * 256;
            int rr = idx >> 5, cc = idx & 31;
            s[rr][cc] = W1[sb + (size_t)(r0 + rr) * H_ + (c0 + cc)];
        }
        __syncthreads();
        #pragma unroll
        for (int k = 0; k < 4; ++k) {
            int idx = threadIdx.x + k * 256;
            int rr = idx >> 5, cc = idx & 31;
            W1T[sb + (size_t)(c0 + rr) * D_ + (r0 + cc)] =
                __float2half_rn(s[cc][rr]);
        }
    }
}

// ---------------------------------------------------------------------------
// Kernel 2: batched expert GEMM (fp16 mma.sync) + fused W2 transpose blocks.
//   z <  32: CTA tile 128x128, 8 warps of 64x32, BK=64, 3-stage cp.async,
//            2 CTA/SM, af-fragment double-buffered.
//   z >= 32 (G1 only): W2 [E][H][D] -> W2T [E][D][H] transpose+convert.
// ---------------------------------------------------------------------------
#define STAGE_BYTES 32768          // A 16KB + B 16KB
#define GEMM_SMEM   (3 * STAGE_BYTES)

template <bool G1>   // true: relu + fp16 out; false: f32 out
__global__ __launch_bounds__(256, 2)
void moe_gemm_kernel(const __half* __restrict__ A,
                     const __half* __restrict__ BT,
                     const float* __restrict__ biasAll,
                     float* __restrict__ outF,
                     __half* __restrict__ outH,
                     int K, int Nt,
                     const float* __restrict__ W2src,
                     __half* __restrict__ W2T)
{
    extern __shared__ char smem[];

    // graph-replay counter reset (stream-ordered after prep kernel)
    if (G1 && blockIdx.x == 0 && blockIdx.y == 0 && blockIdx.z == 0 &&
        threadIdx.x == 0)
        g_prep_done = 0;

    if (G1 && blockIdx.z >= B_) {
        // ---- fused W2 transpose ----
        float (*s)[33] = reinterpret_cast<float(*)[33]>(smem);
        const int e = blockIdx.z - B_;
        const int g = blockIdx.y * gridDim.x + blockIdx.x;  // 0..63
        const size_t sb = (size_t)e * H_ * D_;
        #pragma unroll 1
        for (int i = 0; i < 16; ++i) {
            const int t = g * 16 + i;         // 0..1023
            const int ct = t & 15;            // D tiles
            const int rt = t >> 4;            // H tiles
            const int c0 = ct * 32, r0 = rt * 32;
            __syncthreads();
            #pragma unroll
            for (int k = 0; k < 4; ++k) {
                int idx = threadIdx.x + k * 256;
                int rr = idx >> 5, cc = idx & 31;
                s[rr][cc] = W2src[sb + (size_t)(r0 + rr) * D_ + (c0 + cc)];
            }
            __syncthreads();
            #pragma unroll
            for (int k = 0; k < 4; ++k) {
                int idx = threadIdx.x + k * 256;
                int rr = idx >> 5, cc = idx & 31;
                W2T[sb + (size_t)(c0 + rr) * H_ + (r0 + cc)] =
                    __float2half_rn(s[cc][rr]);
            }
        }
        return;
    }

    const uint32_t sbase = smem_to_u32(smem);
    const int tid  = threadIdx.x;
    const int lane = tid & 31;
    const int wid  = tid >> 5;
    const int warp_m = wid & 1;
    const int warp_n = wid >> 1;

    const int b  = blockIdx.z;
    const int e  = g_chosen[b];
    const int m0 = blockIdx.y * 128;
    const int n0 = blockIdx.x * 128;

    const __half* Ag = A  + (size_t)b * T_ * K + (size_t)m0 * K;
    const __half* Bg = BT + (size_t)e * Nt * K + (size_t)n0 * K;

    const int ltile = lane >> 3;
    const int lr    = lane & 7;
    const uint32_t xr = (uint32_t)lr << 4;
    const uint32_t baseA = (uint32_t)(warp_m * 64 + (ltile & 1) * 8 + lr) * 128u;
    const uint32_t kcA   = (uint32_t)(ltile >> 1) * 16u;
    const uint32_t baseB = (uint32_t)(warp_n * 32 + (ltile >> 1) * 8 + lr) * 128u;
    const uint32_t kcB   = (uint32_t)(ltile & 1) * 16u;

    float acc[4][4][4];
    #pragma unroll
    for (int mi = 0; mi < 4; ++mi)
        #pragma unroll
        for (int ni = 0; ni < 4; ++ni)
            #pragma unroll
            for (int i = 0; i < 4; ++i) acc[mi][ni][i] = 0.0f;

    const int KB = K >> 6;

    auto load_stage = [&](int stage_idx, int k0) {
        const uint32_t stg = sbase + (uint32_t)stage_idx * STAGE_BYTES;
        #pragma unroll
        for (int i = 0; i < 4; ++i) {
            const int q = tid + i * 256;
            const int row = q >> 3, j = q & 7;
            const uint32_t soff = (uint32_t)row * 128u +
                                  (((uint32_t)j * 16u) ^ (((uint32_t)(row & 7)) << 4));
            cp16(stg + soff,          Ag + (size_t)row * K + k0 + j * 8);
            cp16(stg + 16384u + soff, Bg + (size_t)row * K + k0 + j * 8);
        }
        CP_COMMIT();
    };

    load_stage(0, 0);
    load_stage(1, 64);

    uint32_t af[2][4][4], bf[4][2];

    auto load_af = [&](int buf, uint32_t sA, int kk) {
        const uint32_t kA = ((uint32_t)(kk * 32) + kcA) ^ xr;
        #pragma unroll
        for (int mi = 0; mi < 4; ++mi)
            ldsm4(af[buf][mi], sA + baseA + mi * 2048u + kA);
    };
    auto load_bf = [&](uint32_t sB, int kk) {
        const uint32_t kB = ((uint32_t)(kk * 32) + kcB) ^ xr;
        #pragma unroll
        for (int pi = 0; pi < 2; ++pi) {
            uint32_t t4[4];
            ldsm4(t4, sB + baseB + pi * 2048u + kB);
            bf[2*pi][0]   = t4[0]; bf[2*pi][1]   = t4[1];
            bf[2*pi+1][0] = t4[2]; bf[2*pi+1][1] = t4[3];
        }
    };

    for (int kb = 0; kb < KB; ++kb) {
        CP_WAIT1();
        __syncthreads();
        if (kb + 2 < KB) load_stage((kb + 2) % 3, (kb + 2) << 6);
        else CP_COMMIT();

        const uint32_t stg = sbase + (uint32_t)(kb % 3) * STAGE_BYTES;
        const uint32_t sA = stg, sB = stg + 16384u;

        load_af(0, sA, 0);
        #pragma unroll
        for (int kk = 0; kk < 4; ++kk) {
            load_bf(sB, kk);
            if (kk < 3) load_af((kk + 1) & 1, sA, kk + 1);
            #pragma unroll
            for (int mi = 0; mi < 4; ++mi)
                #pragma unroll
                for (int ni = 0; ni < 4; ++ni)
                    mma16816(acc[mi][ni], af[kk & 1][mi], bf[ni]);
        }
    }

    // ---- epilogue ----
    const int gm = m0 + warp_m * 64;
    const int gncol = n0 + warp_n * 32;
    #pragma unroll
    for (int mi = 0; mi < 4; ++mi) {
        const int row0 = gm + mi * 16 + (lane >> 2);
        #pragma unroll
        for (int ni = 0; ni < 4; ++ni) {
            const int col = gncol + ni * 8 + (lane & 3) * 2;
            const float2 bv = *reinterpret_cast<const float2*>(
                biasAll + (size_t)e * Nt + col);
            float v00 = acc[mi][ni][0] + bv.x;
            float v01 = acc[mi][ni][1] + bv.y;
            float v10 = acc[mi][ni][2] + bv.x;
            float v11 = acc[mi][ni][3] + bv.y;
            const size_t o0 = ((size_t)b * T_ + row0) * Nt + col;
            const size_t o1 = ((size_t)b * T_ + row0 + 8) * Nt + col;
            if (G1) {
                v00 = fmaxf(v00, 0.0f); v01 = fmaxf(v01, 0.0f);
                v10 = fmaxf(v10, 0.0f); v11 = fmaxf(v11, 0.0f);
                *reinterpret_cast<__half2*>(outH + o0) =
                    __halves2half2(__float2half_rn(v00), __float2half_rn(v01));
                *reinterpret_cast<__half2*>(outH + o1) =
                    __halves2half2(__float2half_rn(v10), __float2half_rn(v11));
            } else {
                *reinterpret_cast<float2*>(outF + o0) = make_float2(v00, v01);
                *reinterpret_cast<float2*>(outF + o1) = make_float2(v10, v11);
            }
        }
    }
}

// ---------------------------------------------------------------------------
// kernel_launch
// ---------------------------------------------------------------------------
extern "C" void kernel_launch(void* const* d_in, const int* in_sizes, int n_in,
                              void* d_out, int out_size)
{
    const float* x  = (const float*)d_in[0];
    const float* Wp = (const float*)d_in[1];
    const float* bp = (const float*)d_in[2];
    const float* W1 = (const float*)d_in[3];
    const float* b1 = (const float*)d_in[4];
    const float* W2 = (const float*)d_in[5];
    const float* b2 = (const float*)d_in[6];
    float* out = (float*)d_out;

    const long long FINAL_N = (long long)B_ * T_ * D_;
    float* probs_out  = nullptr;
    float* chosen_out = nullptr;
    if ((long long)out_size >= FINAL_N + (long long)B_ * E_)
        probs_out = out + FINAL_N;
    if ((long long)out_size >= FINAL_N + (long long)B_ * E_ + B_)
        chosen_out = out + FINAL_N + (long long)B_ * E_;

    __half *xh, *hh, *w1t, *w2t;
    float* pool_part;
    cudaGetSymbolAddress((void**)&xh, g_x_h);
    cudaGetSymbolAddress((void**)&hh, g_h_h);
    cudaGetSymbolAddress((void**)&w1t, g_W1T);
    cudaGetSymbolAddress((void**)&w2t, g_W2T);
    cudaGetSymbolAddress((void**)&pool_part, g_pool_part);

    cudaFuncSetAttribute(moe_gemm_kernel<true>,
                         cudaFuncAttributeMaxDynamicSharedMemorySize, GEMM_SMEM);
    cudaFuncSetAttribute(moe_gemm_kernel<false>,
                         cudaFuncAttributeMaxDynamicSharedMemorySize, GEMM_SMEM);

    // 1) prep: x->fp16 + pool partials (z=0), W1 transpose (z=1),
    //    gated router (z=2)
    prep_kernel<<<dim3(32, 32, 3), 256>>>(x, xh, pool_part, W1, w1t,
                                          Wp, bp, probs_out, chosen_out);

    // 2) GEMM1 (z<32) + fused W2 transpose (z=32..39)
    moe_gemm_kernel<true><<<dim3(H_ / 128, T_ / 128, B_ + 8), 256, GEMM_SMEM>>>(
        xh, w1t, b1, nullptr, hh, D_, H_, W2, w2t);

    // 3) GEMM2
    moe_gemm_kernel<false><<<dim3(D_ / 128, T_ / 128, B_), 256, GEMM_SMEM>>>(
        hh, w2t, b2, out, nullptr, H_, D_, nullptr, nullptr);
}

// round 11
// speedup vs baseline: 1.5737x; 1.0589x over previous
#include <cuda_runtime.h>
#include <cuda_fp16.h>
#include <cstdint>

#define B_  32
#define T_  512
#define D_  512
#define E_  8
#define H_  2048

// ---------------------------------------------------------------------------
// Device scratch
// ---------------------------------------------------------------------------
__device__ int    g_chosen[B_];
__device__ int    g_prep_done;       // xconv blocks finished (target 1024)
__device__ float  g_pool_part[B_ * 32 * D_];
__device__ __half g_x_h[(size_t)B_ * T_ * D_];            // 16 MB
__device__ __half g_h_h[(size_t)B_ * T_ * H_];            // 64 MB
__device__ __half g_W1h[(size_t)E_ * D_ * H_];            // [E][D][H]  (K-major rows = n-contig)
__device__ __half g_W2h[(size_t)E_ * H_ * D_];            // [E][H][D]

// ---------------------------------------------------------------------------
// PTX helpers (sm_80-baseline only)
// ---------------------------------------------------------------------------
__device__ __forceinline__ uint32_t smem_to_u32(const void* p) {
    uint32_t a;
    asm("{ .reg .u64 t; cvta.to.shared.u64 t, %1; cvt.u32.u64 %0, t; }"
        : "=r"(a) : "l"(p));
    return a;
}

__device__ __forceinline__ void cp16(uint32_t dst, const void* src) {
    asm volatile("cp.async.cg.shared.global [%0], [%1], 16;"
                 :: "r"(dst), "l"(src));
}
#define CP_COMMIT() asm volatile("cp.async.commit_group;" ::: "memory")
#define CP_WAIT1()  asm volatile("cp.async.wait_group 1;"  ::: "memory")

__device__ __forceinline__ void ldsm4(uint32_t* d, uint32_t addr) {
    asm volatile("ldmatrix.sync.aligned.m8n8.x4.shared.b16 {%0,%1,%2,%3}, [%4];"
                 : "=r"(d[0]), "=r"(d[1]), "=r"(d[2]), "=r"(d[3])
                 : "r"(addr));
}

__device__ __forceinline__ void ldsm4t(uint32_t* d, uint32_t addr) {
    asm volatile("ldmatrix.sync.aligned.m8n8.x4.trans.shared.b16 {%0,%1,%2,%3}, [%4];"
                 : "=r"(d[0]), "=r"(d[1]), "=r"(d[2]), "=r"(d[3])
                 : "r"(addr));
}

__device__ __forceinline__ void mma16816(float* c, const uint32_t* a,
                                         const uint32_t* b) {
    asm volatile(
        "mma.sync.aligned.m16n8k16.row.col.f32.f16.f16.f32 "
        "{%0,%1,%2,%3}, {%4,%5,%6,%7}, {%8,%9}, {%0,%1,%2,%3};"
        : "+f"(c[0]), "+f"(c[1]), "+f"(c[2]), "+f"(c[3])
        : "r"(a[0]), "r"(a[1]), "r"(a[2]), "r"(a[3]),
          "r"(b[0]), "r"(b[1]));
}

// ---------------------------------------------------------------------------
// Kernel 1: merged prep, grid (32, 32, 3), 256 threads.
//   z==0: x -> fp16 + pooled partials; publishes completion via g_prep_done.
//   z==1: streaming convert W1 and W2 f32 -> fp16 (same layout, no transpose).
//   z==2 (y==0, x<32): router for batch x, gated on all z==0 blocks done.
// ---------------------------------------------------------------------------
__global__ __launch_bounds__(256)
void prep_kernel(const float* __restrict__ x,
                 __half* __restrict__ xh,
                 float* __restrict__ pool_part,
                 const float* __restrict__ W1,
                 __half* __restrict__ W1h,
                 const float* __restrict__ W2,
                 __half* __restrict__ W2h,
                 const float* __restrict__ Wp,
                 const float* __restrict__ bp,
                 float* __restrict__ probs_out,
                 float* __restrict__ chosen_out)
{
    if (blockIdx.z == 0) {
        const int b  = blockIdx.x;
        const int tc = blockIdx.y;
        const int d0 = threadIdx.x * 2;

        float s0 = 0.0f, s1 = 0.0f;
        #pragma unroll 4
        for (int r = 0; r < 16; ++r) {
            const int t = tc * 16 + r;
            const size_t off = ((size_t)b * T_ + t) * D_ + d0;
            const float2 v = *reinterpret_cast<const float2*>(x + off);
            s0 += v.x; s1 += v.y;
            *reinterpret_cast<__half2*>(xh + off) =
                __halves2half2(__float2half_rn(v.x), __float2half_rn(v.y));
        }
        *reinterpret_cast<float2*>(pool_part + ((size_t)b * 32 + tc) * D_ + d0) =
            make_float2(s0, s1);
        __threadfence();
        __syncthreads();
        if (threadIdx.x == 0) atomicAdd(&g_prep_done, 1);
        return;
    }

    if (blockIdx.z == 2) {
        if (blockIdx.y != 0 || blockIdx.x >= B_) return;
        const int b = blockIdx.x;

        if (threadIdx.x == 0) {
            while (*(volatile int*)&g_prep_done < 32 * 32) __nanosleep(100);
        }
        __syncthreads();
        __threadfence();

        __shared__ float pooled[D_];
        __shared__ float logits[E_];
        #pragma unroll
        for (int k = 0; k < 2; ++k) {
            const int d = threadIdx.x + k * 256;
            float s = 0.0f;
            #pragma unroll
            for (int p = 0; p < 32; ++p)
                s += pool_part[((size_t)b * 32 + p) * D_ + d];
            pooled[d] = s * (1.0f / (float)T_);
        }
        __syncthreads();

        const int warp = threadIdx.x >> 5, lane = threadIdx.x & 31;
        {
            float s = 0.0f;
            #pragma unroll
            for (int k = 0; k < 16; ++k) {
                const int dd = lane + k * 32;
                s += pooled[dd] * Wp[dd * E_ + warp];
            }
            #pragma unroll
            for (int off = 16; off > 0; off >>= 1)
                s += __shfl_down_sync(0xffffffffu, s, off);
            if (lane == 0) logits[warp] = s + bp[warp];
        }
        __syncthreads();

        if (threadIdx.x == 0) {
            float m = logits[0]; int arg = 0;
            #pragma unroll
            for (int e = 1; e < E_; ++e)
                if (logits[e] > m) { m = logits[e]; arg = e; }
            float ex[E_], sum = 0.0f;
            #pragma unroll
            for (int e = 0; e < E_; ++e) { ex[e] = expf(logits[e] - m); sum += ex[e]; }
            const float inv = 1.0f / sum;
            if (probs_out) {
                #pragma unroll
                for (int e = 0; e < E_; ++e) probs_out[b * E_ + e] = ex[e] * inv;
            }
            if (chosen_out) chosen_out[b] = (float)arg;
            g_chosen[b] = arg;
        }
        return;
    }

    // ---- z==1: streaming weight convert (no transpose) ----
    // 1024 blocks; g < 512 -> W1 chunk g; g >= 512 -> W2 chunk g-512.
    // Each block: 16384 contiguous f32 -> fp16.
    {
        const int g = blockIdx.y * 32 + blockIdx.x;
        const float* src = (g < 512) ? (W1 + (size_t)g * 16384)
                                     : (W2 + (size_t)(g - 512) * 16384);
        __half* dst = (g < 512) ? (W1h + (size_t)g * 16384)
                                : (W2h + (size_t)(g - 512) * 16384);
        #pragma unroll
        for (int i = 0; i < 16; ++i) {
            const int idx = (threadIdx.x + i * 256) * 4;
            const float4 v = *reinterpret_cast<const float4*>(src + idx);
            __half2 h0 = __halves2half2(__float2half_rn(v.x), __float2half_rn(v.y));
            __half2 h1 = __halves2half2(__float2half_rn(v.z), __float2half_rn(v.w));
            uint2 pk;
            pk.x = *reinterpret_cast<uint32_t*>(&h0);
            pk.y = *reinterpret_cast<uint32_t*>(&h1);
            *reinterpret_cast<uint2*>(dst + idx) = pk;
        }
    }
}

// ---------------------------------------------------------------------------
// Kernel 2: batched expert GEMM, fp16 mma.sync.
//   C[b] = act( A[b] @ W[e] + bias[e] )
//   A: [B][T][K]   fp16, K-contiguous (row-major, ldmatrix non-trans)
//   W: [E][K][Nt]  fp16, N-contiguous (row-major B, ldmatrix.trans)
// CTA tile 128x128, 8 warps of 64x32, BK=64, 3-stage cp.async, 2 CTA/SM.
// Stage: A 16KB (128 rows x 128B, XOR-16B swz) + B 16KB (64 rows x 256B, XOR swz).
// ---------------------------------------------------------------------------
#define STAGE_BYTES 32768
#define GEMM_SMEM   (3 * STAGE_BYTES)

template <bool G1>   // true: relu + fp16 out; false: f32 out
__global__ __launch_bounds__(256, 2)
void moe_gemm_kernel(const __half* __restrict__ A,
                     const __half* __restrict__ W,
                     const float* __restrict__ biasAll,
                     float* __restrict__ outF,
                     __half* __restrict__ outH,
                     int K, int Nt)
{
    extern __shared__ char smem[];

    // graph-replay counter reset (stream-ordered after prep kernel)
    if (G1 && blockIdx.x == 0 && blockIdx.y == 0 && blockIdx.z == 0 &&
        threadIdx.x == 0)
        g_prep_done = 0;

    const uint32_t sbase = smem_to_u32(smem);
    const int tid  = threadIdx.x;
    const int lane = tid & 31;
    const int wid  = tid >> 5;
    const int warp_m = wid & 1;          // 2 warps along M (64 each)
    const int warp_n = wid >> 1;         // 4 warps along N (32 each)

    const int b  = blockIdx.z;
    const int e  = g_chosen[b];
    const int m0 = blockIdx.y * 128;
    const int n0 = blockIdx.x * 128;

    const __half* Ag = A + (size_t)b * T_ * K + (size_t)m0 * K;
    const __half* Bg = W + (size_t)e * K * Nt + n0;     // row k: + k*Nt

    // A ldmatrix addressing (K-major rows of 128B, XOR-16B swizzle)
    const int ltile = lane >> 3;
    const int lr    = lane & 7;
    const uint32_t xr = (uint32_t)lr << 4;
    const uint32_t baseA = (uint32_t)(warp_m * 64 + (ltile & 1) * 8 + lr) * 128u;
    const uint32_t kcA   = (uint32_t)(ltile >> 1) * 16u;

    // B ldmatrix.trans addressing (rows = k, 256B each = 128 n fp16).
    // For trans-load p (p=0,1): 16k x 16n region at n = warp_n*32 + p*16.
    //   lane group g2 = lane>>3: rowLocal = (g2&1)*8 + lr, ncol16 = warp_n*4 + p*2 + (g2>>1)
    //   addr = rowLocal*256 + ((ncol16 ^ lr) * 16)        [rowLocal & 7 == lr]
    const uint32_t rowL  = (uint32_t)((ltile & 1) * 8 + lr);
    const uint32_t addrB0 = rowL * 256u +
        ((((uint32_t)(warp_n * 4 + 0 * 2) + (uint32_t)(ltile >> 1)) ^ (uint32_t)lr) << 4);
    const uint32_t addrB1 = rowL * 256u +
        ((((uint32_t)(warp_n * 4 + 1 * 2) + (uint32_t)(ltile >> 1)) ^ (uint32_t)lr) << 4);

    float acc[4][4][4];
    #pragma unroll
    for (int mi = 0; mi < 4; ++mi)
        #pragma unroll
        for (int ni = 0; ni < 4; ++ni)
            #pragma unroll
            for (int i = 0; i < 4; ++i) acc[mi][ni][i] = 0.0f;

    const int KB = K >> 6;

    auto load_stage = [&](int stage_idx, int k0) {
        const uint32_t stg = sbase + (uint32_t)stage_idx * STAGE_BYTES;
        // A: 128 rows x 8 chunks of 16B
        #pragma unroll
        for (int i = 0; i < 4; ++i) {
            const int q = tid + i * 256;
            const int row = q >> 3, j = q & 7;
            const uint32_t soff = (uint32_t)row * 128u +
                                  (((uint32_t)j ^ ((uint32_t)row & 7u)) << 4);
            cp16(stg + soff, Ag + (size_t)row * K + k0 + j * 8);
        }
        // B: 64 rows x 16 chunks of 16B (row k0+row, cols n0 + j*8)
        #pragma unroll
        for (int i = 0; i < 4; ++i) {
            const int q = tid + i * 256;
            const int row = q >> 4, j = q & 15;
            const uint32_t soff = (uint32_t)row * 256u +
                                  (((uint32_t)j ^ ((uint32_t)row & 7u)) << 4);
            cp16(stg + 16384u + soff, Bg + (size_t)(k0 + row) * Nt + j * 8);
        }
        CP_COMMIT();
    };

    load_stage(0, 0);
    load_stage(1, 64);

    uint32_t af[2][4][4], bf[4][2];

    auto load_af = [&](int buf, uint32_t sA, int kk) {
        const uint32_t kA = ((uint32_t)(kk * 32) + kcA) ^ xr;
        #pragma unroll
        for (int mi = 0; mi < 4; ++mi)
            ldsm4(af[buf][mi], sA + baseA + mi * 2048u + kA);
    };
    // trans-load: m0=(k0:8, n0:8)^T, m1=(k8:16, n0:8)^T, m2=(k0:8, n8:16)^T, m3=...
    // -> bf[n-block0] = {m0, m1}, bf[n-block1] = {m2, m3}
    auto load_bf = [&](uint32_t sB, int kk) {
        const uint32_t kOff = (uint32_t)kk * 4096u;   // 16 rows * 256B
        uint32_t t4[4];
        ldsm4t(t4, sB + kOff + addrB0);
        bf[0][0] = t4[0]; bf[0][1] = t4[1];
        bf[1][0] = t4[2]; bf[1][1] = t4[3];
        ldsm4t(t4, sB + kOff + addrB1);
        bf[2][0] = t4[0]; bf[2][1] = t4[1];
        bf[3][0] = t4[2]; bf[3][1] = t4[3];
    };

    for (int kb = 0; kb < KB; ++kb) {
        CP_WAIT1();
        __syncthreads();
        if (kb + 2 < KB) load_stage((kb + 2) % 3, (kb + 2) << 6);
        else CP_COMMIT();

        const uint32_t stg = sbase + (uint32_t)(kb % 3) * STAGE_BYTES;
        const uint32_t sA = stg, sB = stg + 16384u;

        load_af(0, sA, 0);
        #pragma unroll
        for (int kk = 0; kk < 4; ++kk) {
            load_bf(sB, kk);
            if (kk < 3) load_af((kk + 1) & 1, sA, kk + 1);
            #pragma unroll
            for (int mi = 0; mi < 4; ++mi)
                #pragma unroll
                for (int ni = 0; ni < 4; ++ni)
                    mma16816(acc[mi][ni], af[kk & 1][mi], bf[ni]);
        }
    }

    // ---- epilogue ----
    const int gm = m0 + warp_m * 64;
    const int gncol = n0 + warp_n * 32;
    #pragma unroll
    for (int mi = 0; mi < 4; ++mi) {
        const int row0 = gm + mi * 16 + (lane >> 2);
        #pragma unroll
        for (int ni = 0; ni < 4; ++ni) {
            const int col = gncol + ni * 8 + (lane & 3) * 2;
            const float2 bv = *reinterpret_cast<const float2*>(
                biasAll + (size_t)e * Nt + col);
            float v00 = acc[mi][ni][0] + bv.x;
            float v01 = acc[mi][ni][1] + bv.y;
            float v10 = acc[mi][ni][2] + bv.x;
            float v11 = acc[mi][ni][3] + bv.y;
            const size_t o0 = ((size_t)b * T_ + row0) * Nt + col;
            const size_t o1 = ((size_t)b * T_ + row0 + 8) * Nt + col;
            if (G1) {
                v00 = fmaxf(v00, 0.0f); v01 = fmaxf(v01, 0.0f);
                v10 = fmaxf(v10, 0.0f); v11 = fmaxf(v11, 0.0f);
                *reinterpret_cast<__half2*>(outH + o0) =
                    __halves2half2(__float2half_rn(v00), __float2half_rn(v01));
                *reinterpret_cast<__half2*>(outH + o1) =
                    __halves2half2(__float2half_rn(v10), __float2half_rn(v11));
            } else {
                *reinterpret_cast<float2*>(outF + o0) = make_float2(v00, v01);
                *reinterpret_cast<float2*>(outF + o1) = make_float2(v10, v11);
            }
        }
    }
}

// ---------------------------------------------------------------------------
// kernel_launch
// ---------------------------------------------------------------------------
extern "C" void kernel_launch(void* const* d_in, const int* in_sizes, int n_in,
                              void* d_out, int out_size)
{
    const float* x  = (const float*)d_in[0];
    const float* Wp = (const float*)d_in[1];
    const float* bp = (const float*)d_in[2];
    const float* W1 = (const float*)d_in[3];
    const float* b1 = (const float*)d_in[4];
    const float* W2 = (const float*)d_in[5];
    const float* b2 = (const float*)d_in[6];
    float* out = (float*)d_out;

    const long long FINAL_N = (long long)B_ * T_ * D_;
    float* probs_out  = nullptr;
    float* chosen_out = nullptr;
    if ((long long)out_size >= FINAL_N + (long long)B_ * E_)
        probs_out = out + FINAL_N;
    if ((long long)out_size >= FINAL_N + (long long)B_ * E_ + B_)
        chosen_out = out + FINAL_N + (long long)B_ * E_;

    __half *xh, *hh, *w1h, *w2h;
    float* pool_part;
    cudaGetSymbolAddress((void**)&xh, g_x_h);
    cudaGetSymbolAddress((void**)&hh, g_h_h);
    cudaGetSymbolAddress((void**)&w1h, g_W1h);
    cudaGetSymbolAddress((void**)&w2h, g_W2h);
    cudaGetSymbolAddress((void**)&pool_part, g_pool_part);

    cudaFuncSetAttribute(moe_gemm_kernel<true>,
                         cudaFuncAttributeMaxDynamicSharedMemorySize, GEMM_SMEM);
    cudaFuncSetAttribute(moe_gemm_kernel<false>,
                         cudaFuncAttributeMaxDynamicSharedMemorySize, GEMM_SMEM);

    // 1) prep: x->fp16 + pool partials (z=0), W1/W2 streaming convert (z=1),
    //    gated router (z=2)
    prep_kernel<<<dim3(32, 32, 3), 256>>>(x, xh, pool_part, W1, w1h, W2, w2h,
                                          Wp, bp, probs_out, chosen_out);

    // 2) GEMM1: h = relu(x @ W1[e] + b1[e]) : M=512, N=2048, K=512
    moe_gemm_kernel<true><<<dim3(H_ / 128, T_ / 128, B_), 256, GEMM_SMEM>>>(
        xh, w1h, b1, nullptr, hh, D_, H_);

    // 3) GEMM2: final = h @ W2[e] + b2[e]   : M=512, N=512, K=2048
    moe_gemm_kernel<false><<<dim3(D_ / 128, T_ / 128, B_), 256, GEMM_SMEM>>>(
        hh, w2h, b2, out, nullptr, H_, D_);
}

// round 12
// speedup vs baseline: 1.8017x; 1.1449x over previous
#include <cuda_runtime.h>
#include <cuda_fp16.h>
#include <cuda.h>
#include <cstdint>

#define B_  32
#define T_  512
#define D_  512
#define E_  8
#define H_  2048

// ---------------------------------------------------------------------------
// Device scratch
// ---------------------------------------------------------------------------
__device__ int    g_chosen[B_];
__device__ int    g_prep_done;
__device__ float  g_pool_part[B_ * 32 * D_];
__device__ __half g_x_h[(size_t)B_ * T_ * D_];            // 16 MB
__device__ __half g_h_h[(size_t)B_ * T_ * H_];            // 64 MB
__device__ __half g_W1h[(size_t)E_ * D_ * H_];            // [E][D][H]
__device__ __half g_W2h[(size_t)E_ * H_ * D_];            // [E][H][D]

// ---------------------------------------------------------------------------
// PTX helpers
// ---------------------------------------------------------------------------
__device__ __forceinline__ uint32_t smem_to_u32(const void* p) {
    uint32_t a;
    asm("{ .reg .u64 t; cvta.to.shared.u64 t, %1; cvt.u32.u64 %0, t; }"
        : "=r"(a) : "l"(p));
    return a;
}

__device__ __forceinline__ void ldsm4(uint32_t* d, uint32_t addr) {
    asm volatile("ldmatrix.sync.aligned.m8n8.x4.shared.b16 {%0,%1,%2,%3}, [%4];"
                 : "=r"(d[0]), "=r"(d[1]), "=r"(d[2]), "=r"(d[3])
                 : "r"(addr));
}
__device__ __forceinline__ void ldsm4t(uint32_t* d, uint32_t addr) {
    asm volatile("ldmatrix.sync.aligned.m8n8.x4.trans.shared.b16 {%0,%1,%2,%3}, [%4];"
                 : "=r"(d[0]), "=r"(d[1]), "=r"(d[2]), "=r"(d[3])
                 : "r"(addr));
}
__device__ __forceinline__ void mma16816(float* c, const uint32_t* a,
                                         const uint32_t* b) {
    asm volatile(
        "mma.sync.aligned.m16n8k16.row.col.f32.f16.f16.f32 "
        "{%0,%1,%2,%3}, {%4,%5,%6,%7}, {%8,%9}, {%0,%1,%2,%3};"
        : "+f"(c[0]), "+f"(c[1]), "+f"(c[2]), "+f"(c[3])
        : "r"(a[0]), "r"(a[1]), "r"(a[2]), "r"(a[3]),
          "r"(b[0]), "r"(b[1]));
}

#define MBARRIER_INIT(addr, count) \
    asm volatile("mbarrier.init.shared.b64 [%0], %1;" \
        :: "r"((uint32_t)(addr)), "r"((uint32_t)(count)) : "memory")
#define MBARRIER_EXPECT_TX(addr, bytes) \
    asm volatile("mbarrier.arrive.expect_tx.shared.b64 _, [%0], %1;" \
        :: "r"((uint32_t)(addr)), "r"((uint32_t)(bytes)) : "memory")
#define MBARRIER_WAIT_PARITY(mbar_smem_addr, phase_parity) do { \
    uint32_t _mbar = (uint32_t)(mbar_smem_addr); \
    uint32_t _parity = (uint32_t)(phase_parity); \
    uint32_t _done; \
    asm volatile("{\n\t.reg .pred p;\n\t" \
        "mbarrier.try_wait.parity.acquire.cta.shared::cta.b64 p, [%1], %2;\n\t" \
        "selp.b32 %0, 1, 0, p;\n\t}" \
        : "=r"(_done) : "r"(_mbar), "r"(_parity) : "memory"); \
    if (!_done) { \
        asm volatile("{\n\t.reg .pred P1;\n\t" \
            "WAIT_LOOP_%=:\n\t" \
            "mbarrier.try_wait.parity.acquire.cta.shared::cta.b64 P1, [%0], %1, 0x989680;\n\t" \
            "@P1 bra.uni WAIT_DONE_%=;\n\t" \
            "bra.uni WAIT_LOOP_%=;\n\t" \
            "WAIT_DONE_%=:\n\t}" \
            :: "r"(_mbar), "r"(_parity) : "memory"); \
    } \
} while (0)

#define TMA_LOAD_3D(smem_addr, tmap_ptr, c0, c1, c2, mbar) \
    asm volatile("cp.async.bulk.tensor.3d.shared::cta.global.tile.mbarrier::complete_tx::bytes " \
        "[%0], [%1, {%2, %3, %4}], [%5];" \
        :: "r"((uint32_t)(smem_addr)), "l"(tmap_ptr), \
           "r"((int32_t)(c0)), "r"((int32_t)(c1)), "r"((int32_t)(c2)), \
           "r"((uint32_t)(mbar)) : "memory")

// ---------------------------------------------------------------------------
// Kernel 1: merged prep (unchanged from R11 — proven).
// ---------------------------------------------------------------------------
__global__ __launch_bounds__(256)
void prep_kernel(const float* __restrict__ x,
                 __half* __restrict__ xh,
                 float* __restrict__ pool_part,
                 const float* __restrict__ W1,
                 __half* __restrict__ W1h,
                 const float* __restrict__ W2,
                 __half* __restrict__ W2h,
                 const float* __restrict__ Wp,
                 const float* __restrict__ bp,
                 float* __restrict__ probs_out,
                 float* __restrict__ chosen_out)
{
    if (blockIdx.z == 0) {
        const int b  = blockIdx.x;
        const int tc = blockIdx.y;
        const int d0 = threadIdx.x * 2;

        float s0 = 0.0f, s1 = 0.0f;
        #pragma unroll 4
        for (int r = 0; r < 16; ++r) {
            const int t = tc * 16 + r;
            const size_t off = ((size_t)b * T_ + t) * D_ + d0;
            const float2 v = *reinterpret_cast<const float2*>(x + off);
            s0 += v.x; s1 += v.y;
            *reinterpret_cast<__half2*>(xh + off) =
                __halves2half2(__float2half_rn(v.x), __float2half_rn(v.y));
        }
        *reinterpret_cast<float2*>(pool_part + ((size_t)b * 32 + tc) * D_ + d0) =
            make_float2(s0, s1);
        __threadfence();
        __syncthreads();
        if (threadIdx.x == 0) atomicAdd(&g_prep_done, 1);
        return;
    }

    if (blockIdx.z == 2) {
        if (blockIdx.y != 0 || blockIdx.x >= B_) return;
        const int b = blockIdx.x;

        if (threadIdx.x == 0) {
            while (*(volatile int*)&g_prep_done < 32 * 32) __nanosleep(100);
        }
        __syncthreads();
        __threadfence();

        __shared__ float pooled[D_];
        __shared__ float logits[E_];
        #pragma unroll
        for (int k = 0; k < 2; ++k) {
            const int d = threadIdx.x + k * 256;
            float s = 0.0f;
            #pragma unroll
            for (int p = 0; p < 32; ++p)
                s += pool_part[((size_t)b * 32 + p) * D_ + d];
            pooled[d] = s * (1.0f / (float)T_);
        }
        __syncthreads();

        const int warp = threadIdx.x >> 5, lane = threadIdx.x & 31;
        {
            float s = 0.0f;
            #pragma unroll
            for (int k = 0; k < 16; ++k) {
                const int dd = lane + k * 32;
                s += pooled[dd] * Wp[dd * E_ + warp];
            }
            #pragma unroll
            for (int off = 16; off > 0; off >>= 1)
                s += __shfl_down_sync(0xffffffffu, s, off);
            if (lane == 0) logits[warp] = s + bp[warp];
        }
        __syncthreads();

        if (threadIdx.x == 0) {
            float m = logits[0]; int arg = 0;
            #pragma unroll
            for (int e = 1; e < E_; ++e)
                if (logits[e] > m) { m = logits[e]; arg = e; }
            float ex[E_], sum = 0.0f;
            #pragma unroll
            for (int e = 0; e < E_; ++e) { ex[e] = expf(logits[e] - m); sum += ex[e]; }
            const float inv = 1.0f / sum;
            if (probs_out) {
                #pragma unroll
                for (int e = 0; e < E_; ++e) probs_out[b * E_ + e] = ex[e] * inv;
            }
            if (chosen_out) chosen_out[b] = (float)arg;
            g_chosen[b] = arg;
        }
        return;
    }

    // ---- z==1: streaming weight convert ----
    {
        const int g = blockIdx.y * 32 + blockIdx.x;
        const float* src = (g < 512) ? (W1 + (size_t)g * 16384)
                                     : (W2 + (size_t)(g - 512) * 16384);
        __half* dst = (g < 512) ? (W1h + (size_t)g * 16384)
                                : (W2h + (size_t)(g - 512) * 16384);
        #pragma unroll
        for (int i = 0; i < 16; ++i) {
            const int idx = (threadIdx.x + i * 256) * 4;
            const float4 v = *reinterpret_cast<const float4*>(src + idx);
            __half2 h0 = __halves2half2(__float2half_rn(v.x), __float2half_rn(v.y));
            __half2 h1 = __halves2half2(__float2half_rn(v.z), __float2half_rn(v.w));
            uint2 pk;
            pk.x = *reinterpret_cast<uint32_t*>(&h0);
            pk.y = *reinterpret_cast<uint32_t*>(&h1);
            *reinterpret_cast<uint2*>(dst + idx) = pk;
        }
    }
}

// ---------------------------------------------------------------------------
// Kernel 2: batched expert GEMM with TMA operand loads.
//   A via tmA: 3D (K, T, B) fp16, box (64, 128), SW128 -> smem 128 rows x 128B
//   B via tmB: 3D (Nt, K, E) fp16, box (64, 64), SW128 -> two 64-row x 128B halves
// CTA tile 128x128, 8 warps of 64x32, BK=64, 3-stage mbarrier pipeline, 2 CTA/SM.
// ---------------------------------------------------------------------------
#define STAGE_BYTES 32768
#define MBAR_OFF    (3 * STAGE_BYTES)
#define GEMM_SMEM   (MBAR_OFF + 128)

template <bool G1>   // true: relu + fp16 out; false: f32 out
__global__ __launch_bounds__(256, 2)
void moe_gemm_kernel(const __grid_constant__ CUtensorMap tmA,
                     const __grid_constant__ CUtensorMap tmB,
                     const float* __restrict__ biasAll,
                     float* __restrict__ outF,
                     __half* __restrict__ outH,
                     int K, int Nt)
{
    extern __shared__ char smem[];

    // graph-replay counter reset (stream-ordered after prep kernel)
    if (G1 && blockIdx.x == 0 && blockIdx.y == 0 && blockIdx.z == 0 &&
        threadIdx.x == 0)
        g_prep_done = 0;

    const uint32_t sbase = smem_to_u32(smem);
    const int tid  = threadIdx.x;
    const int lane = tid & 31;
    const int wid  = tid >> 5;
    const int warp_m = wid & 1;          // 2 warps along M (64 each)
    const int warp_n = wid >> 1;         // 4 warps along N (32 each)

    const int b  = blockIdx.z;
    const int e  = g_chosen[b];
    const int m0 = blockIdx.y * 128;
    const int n0 = blockIdx.x * 128;

    // A ldmatrix addressing (128B rows, SW128: c16 ^= row&7)
    const int ltile = lane >> 3;
    const int lr    = lane & 7;
    const uint32_t xr = (uint32_t)lr << 4;
    const uint32_t baseA = (uint32_t)(warp_m * 64 + (ltile & 1) * 8 + lr) * 128u;
    const uint32_t kcA   = (uint32_t)(ltile >> 1) * 16u;

    // B ldmatrix.trans addressing: half = warp_n>>1, 64-row x 128B blocks.
    const uint32_t bOff = 16384u + (uint32_t)(warp_n >> 1) * 8192u;
    const uint32_t rowL = (uint32_t)((ltile & 1) * 8 + lr);
    const uint32_t cb0  = (uint32_t)((warp_n & 1) * 4 + (ltile >> 1));
    const uint32_t addrB0 = bOff + rowL * 128u + ((cb0 ^ (uint32_t)lr) << 4);
    const uint32_t addrB1 = bOff + rowL * 128u + (((cb0 + 2u) ^ (uint32_t)lr) << 4);

    float acc[4][4][4];
    #pragma unroll
    for (int mi = 0; mi < 4; ++mi)
        #pragma unroll
        for (int ni = 0; ni < 4; ++ni)
            #pragma unroll
            for (int i = 0; i < 4; ++i) acc[mi][ni][i] = 0.0f;

    const int KB = K >> 6;

    const uint32_t mbar0 = sbase + MBAR_OFF;

    auto issue_stage = [&](int s, int kb2) {
        const uint32_t stg = sbase + (uint32_t)s * STAGE_BYTES;
        const uint32_t mb  = mbar0 + (uint32_t)s * 8u;
        const int k0 = kb2 << 6;
        MBARRIER_EXPECT_TX(mb, STAGE_BYTES);
        TMA_LOAD_3D(stg,           &tmA, k0,       m0, b, mb);
        TMA_LOAD_3D(stg + 16384u,  &tmB, n0,       k0, e, mb);
        TMA_LOAD_3D(stg + 24576u,  &tmB, n0 + 64,  k0, e, mb);
    };

    if (tid == 0) {
        MBARRIER_INIT(mbar0 + 0, 1);
        MBARRIER_INIT(mbar0 + 8, 1);
        MBARRIER_INIT(mbar0 + 16, 1);
        asm volatile("fence.proxy.async.shared::cta;" ::: "memory");
    }
    __syncthreads();
    if (tid == 0) {
        issue_stage(0, 0);
        issue_stage(1, 1);
    }

    uint32_t af[2][4][4], bf[4][2];

    auto load_af = [&](int buf, uint32_t stg, int kk) {
        const uint32_t kA = ((uint32_t)(kk * 32) + kcA) ^ xr;
        #pragma unroll
        for (int mi = 0; mi < 4; ++mi)
            ldsm4(af[buf][mi], stg + baseA + mi * 2048u + kA);
    };
    auto load_bf = [&](uint32_t stg, int kk) {
        const uint32_t kOff = (uint32_t)kk * 2048u;   // 16 k-rows * 128B
        uint32_t t4[4];
        ldsm4t(t4, stg + kOff + addrB0);
        bf[0][0] = t4[0]; bf[0][1] = t4[1];
        bf[1][0] = t4[2]; bf[1][1] = t4[3];
        ldsm4t(t4, stg + kOff + addrB1);
        bf[2][0] = t4[0]; bf[2][1] = t4[1];
        bf[3][0] = t4[2]; bf[3][1] = t4[3];
    };

    for (int kb = 0; kb < KB; ++kb) {
        const int s = kb % 3;
        const int par = (kb / 3) & 1;
        MBARRIER_WAIT_PARITY(mbar0 + (uint32_t)s * 8u, par);
        if (tid == 0 && kb + 2 < KB) issue_stage((kb + 2) % 3, kb + 2);

        const uint32_t stg = sbase + (uint32_t)s * STAGE_BYTES;

        load_af(0, stg, 0);
        #pragma unroll
        for (int kk = 0; kk < 4; ++kk) {
            load_bf(stg, kk);
            if (kk < 3) load_af((kk + 1) & 1, stg, kk + 1);
            #pragma unroll
            for (int mi = 0; mi < 4; ++mi)
                #pragma unroll
                for (int ni = 0; ni < 4; ++ni)
                    mma16816(acc[mi][ni], af[kk & 1][mi], bf[ni]);
        }
        __syncthreads();   // stage consumed; safe for TMA overwrite next iters
    }

    // ---- epilogue ----
    const int gm = m0 + warp_m * 64;
    const int gncol = n0 + warp_n * 32;
    #pragma unroll
    for (int mi = 0; mi < 4; ++mi) {
        const int row0 = gm + mi * 16 + (lane >> 2);
        #pragma unroll
        for (int ni = 0; ni < 4; ++ni) {
            const int col = gncol + ni * 8 + (lane & 3) * 2;
            const float2 bv = *reinterpret_cast<const float2*>(
                biasAll + (size_t)e * Nt + col);
            float v00 = acc[mi][ni][0] + bv.x;
            float v01 = acc[mi][ni][1] + bv.y;
            float v10 = acc[mi][ni][2] + bv.x;
            float v11 = acc[mi][ni][3] + bv.y;
            const size_t o0 = ((size_t)b * T_ + row0) * Nt + col;
            const size_t o1 = ((size_t)b * T_ + row0 + 8) * Nt + col;
            if (G1) {
                v00 = fmaxf(v00, 0.0f); v01 = fmaxf(v01, 0.0f);
                v10 = fmaxf(v10, 0.0f); v11 = fmaxf(v11, 0.0f);
                *reinterpret_cast<__half2*>(outH + o0) =
                    __halves2half2(__float2half_rn(v00), __float2half_rn(v01));
                *reinterpret_cast<__half2*>(outH + o1) =
                    __halves2half2(__float2half_rn(v10), __float2half_rn(v11));
            } else {
                *reinterpret_cast<float2*>(outF + o0) = make_float2(v00, v01);
                *reinterpret_cast<float2*>(outF + o1) = make_float2(v10, v11);
            }
        }
    }
}

// ---------------------------------------------------------------------------
// Host: tensormap encoding via driver entry point (no -lcuda needed)
// ---------------------------------------------------------------------------
typedef CUresult (*EncFn)(CUtensorMap*, CUtensorMapDataType, cuuint32_t, void*,
                          const cuuint64_t*, const cuuint64_t*, const cuuint32_t*,
                          const cuuint32_t*, CUtensorMapInterleave,
                          CUtensorMapSwizzle, CUtensorMapL2promotion,
                          CUtensorMapFloatOOBfill);

static EncFn get_encoder()
{
    void* fn = nullptr;
    cudaDriverEntryPointQueryResult st;
#if CUDART_VERSION >= 12050
    cudaGetDriverEntryPointByVersion("cuTensorMapEncodeTiled", &fn, 12000,
                                     cudaEnableDefault, &st);
#else
    cudaGetDriverEntryPoint("cuTensorMapEncodeTiled", &fn,
                            cudaEnableDefault, &st);
#endif
    return (EncFn)fn;
}

static void make_tmap(EncFn enc, CUtensorMap* tm, void* base,
                      uint64_t d0, uint64_t d1, uint64_t d2,
                      uint32_t box0, uint32_t box1)
{
    cuuint64_t dims[3]    = {d0, d1, d2};
    cuuint64_t strides[2] = {d0 * 2, d0 * d1 * 2};
    cuuint32_t box[3]     = {box0, box1, 1};
    cuuint32_t es[3]      = {1, 1, 1};
    enc(tm, CU_TENSOR_MAP_DATA_TYPE_FLOAT16, 3, base, dims, strides, box, es,
        CU_TENSOR_MAP_INTERLEAVE_NONE, CU_TENSOR_MAP_SWIZZLE_128B,
        CU_TENSOR_MAP_L2_PROMOTION_L2_128B, CU_TENSOR_MAP_FLOAT_OOB_FILL_NONE);
}

// ---------------------------------------------------------------------------
// kernel_launch
// ---------------------------------------------------------------------------
extern "C" void kernel_launch(void* const* d_in, const int* in_sizes, int n_in,
                              void* d_out, int out_size)
{
    const float* x  = (const float*)d_in[0];
    const float* Wp = (const float*)d_in[1];
    const float* bp = (const float*)d_in[2];
    const float* W1 = (const float*)d_in[3];
    const float* b1 = (const float*)d_in[4];
    const float* W2 = (const float*)d_in[5];
    const float* b2 = (const float*)d_in[6];
    float* out = (float*)d_out;

    const long long FINAL_N = (long long)B_ * T_ * D_;
    float* probs_out  = nullptr;
    float* chosen_out = nullptr;
    if ((long long)out_size >= FINAL_N + (long long)B_ * E_)
        probs_out = out + FINAL_N;
    if ((long long)out_size >= FINAL_N + (long long)B_ * E_ + B_)
        chosen_out = out + FINAL_N + (long long)B_ * E_;

    __half *xh, *hh, *w1h, *w2h;
    float* pool_part;
    cudaGetSymbolAddress((void**)&xh, g_x_h);
    cudaGetSymbolAddress((void**)&hh, g_h_h);
    cudaGetSymbolAddress((void**)&w1h, g_W1h);
    cudaGetSymbolAddress((void**)&w2h, g_W2h);
    cudaGetSymbolAddress((void**)&pool_part, g_pool_part);

    EncFn enc = get_encoder();
    CUtensorMap tmA1, tmB1, tmA2, tmB2;
    // A1: xh  (K=512, T=512, B=32),  box (64, 128)
    make_tmap(enc, &tmA1, xh,  512, 512, 32, 64, 128);
    // B1: w1h (N=2048, K=512, E=8),  box (64, 64)
    make_tmap(enc, &tmB1, w1h, 2048, 512, 8, 64, 64);
    // A2: hh  (K=2048, T=512, B=32), box (64, 128)
    make_tmap(enc, &tmA2, hh,  2048, 512, 32, 64, 128);
    // B2: w2h (N=512, K=2048, E=8),  box (64, 64)
    make_tmap(enc, &tmB2, w2h, 512, 2048, 8, 64, 64);

    cudaFuncSetAttribute(moe_gemm_kernel<true>,
                         cudaFuncAttributeMaxDynamicSharedMemorySize, GEMM_SMEM);
    cudaFuncSetAttribute(moe_gemm_kernel<false>,
                         cudaFuncAttributeMaxDynamicSharedMemorySize, GEMM_SMEM);

    // 1) prep
    prep_kernel<<<dim3(32, 32, 3), 256>>>(x, xh, pool_part, W1, w1h, W2, w2h,
                                          Wp, bp, probs_out, chosen_out);

    // 2) GEMM1: h = relu(x @ W1[e] + b1[e]) : M=512, N=2048, K=512
    moe_gemm_kernel<true><<<dim3(H_ / 128, T_ / 128, B_), 256, GEMM_SMEM>>>(
        tmA1, tmB1, b1, nullptr, hh, D_, H_);

    // 3) GEMM2: final = h @ W2[e] + b2[e]   : M=512, N=512, K=2048
    moe_gemm_kernel<false><<<dim3(D_ / 128, T_ / 128, B_), 256, GEMM_SMEM>>>(
        tmA2, tmB2, b2, out, nullptr, H_, D_);
}

// round 13
// speedup vs baseline: 1.8142x; 1.0069x over previous
#include <cuda_runtime.h>
#include <cuda_fp16.h>
#include <cuda.h>
#include <cstdint>

#define B_  32
#define T_  512
#define D_  512
#define E_  8
#define H_  2048

// ---------------------------------------------------------------------------
// Device scratch
// ---------------------------------------------------------------------------
__device__ int    g_chosen[B_];
__device__ int    g_prep_done;
__device__ float  g_pool_part[B_ * 32 * D_];
__device__ __half g_x_h[(size_t)B_ * T_ * D_];            // 16 MB
__device__ __half g_h_h[(size_t)B_ * T_ * H_];            // 64 MB
__device__ __half g_W1h[(size_t)E_ * D_ * H_];            // [E][D][H]
__device__ __half g_W2h[(size_t)E_ * H_ * D_];            // [E][H][D]

// ---------------------------------------------------------------------------
// PTX helpers
// ---------------------------------------------------------------------------
__device__ __forceinline__ uint32_t smem_to_u32(const void* p) {
    uint32_t a;
    asm("{ .reg .u64 t; cvta.to.shared.u64 t, %1; cvt.u32.u64 %0, t; }"
        : "=r"(a) : "l"(p));
    return a;
}

__device__ __forceinline__ void ldsm4(uint32_t* d, uint32_t addr) {
    asm volatile("ldmatrix.sync.aligned.m8n8.x4.shared.b16 {%0,%1,%2,%3}, [%4];"
                 : "=r"(d[0]), "=r"(d[1]), "=r"(d[2]), "=r"(d[3])
                 : "r"(addr));
}
__device__ __forceinline__ void ldsm4t(uint32_t* d, uint32_t addr) {
    asm volatile("ldmatrix.sync.aligned.m8n8.x4.trans.shared.b16 {%0,%1,%2,%3}, [%4];"
                 : "=r"(d[0]), "=r"(d[1]), "=r"(d[2]), "=r"(d[3])
                 : "r"(addr));
}
__device__ __forceinline__ void mma16816(float* c, const uint32_t* a,
                                         const uint32_t* b) {
    asm volatile(
        "mma.sync.aligned.m16n8k16.row.col.f32.f16.f16.f32 "
        "{%0,%1,%2,%3}, {%4,%5,%6,%7}, {%8,%9}, {%0,%1,%2,%3};"
        : "+f"(c[0]), "+f"(c[1]), "+f"(c[2]), "+f"(c[3])
        : "r"(a[0]), "r"(a[1]), "r"(a[2]), "r"(a[3]),
          "r"(b[0]), "r"(b[1]));
}

#define MBARRIER_INIT(addr, count) \
    asm volatile("mbarrier.init.shared.b64 [%0], %1;" \
        :: "r"((uint32_t)(addr)), "r"((uint32_t)(count)) : "memory")
#define MBARRIER_EXPECT_TX(addr, bytes) \
    asm volatile("mbarrier.arrive.expect_tx.shared.b64 _, [%0], %1;" \
        :: "r"((uint32_t)(addr)), "r"((uint32_t)(bytes)) : "memory")
#define MBARRIER_WAIT_PARITY(mbar_smem_addr, phase_parity) do { \
    uint32_t _mbar = (uint32_t)(mbar_smem_addr); \
    uint32_t _parity = (uint32_t)(phase_parity); \
    uint32_t _done; \
    asm volatile("{\n\t.reg .pred p;\n\t" \
        "mbarrier.try_wait.parity.acquire.cta.shared::cta.b64 p, [%1], %2;\n\t" \
        "selp.b32 %0, 1, 0, p;\n\t}" \
        : "=r"(_done) : "r"(_mbar), "r"(_parity) : "memory"); \
    if (!_done) { \
        asm volatile("{\n\t.reg .pred P1;\n\t" \
            "WAIT_LOOP_%=:\n\t" \
            "mbarrier.try_wait.parity.acquire.cta.shared::cta.b64 P1, [%0], %1, 0x989680;\n\t" \
            "@P1 bra.uni WAIT_DONE_%=;\n\t" \
            "bra.uni WAIT_LOOP_%=;\n\t" \
            "WAIT_DONE_%=:\n\t}" \
            :: "r"(_mbar), "r"(_parity) : "memory"); \
    } \
} while (0)

#define TMA_LOAD_3D(smem_addr, tmap_ptr, c0, c1, c2, mbar) \
    asm volatile("cp.async.bulk.tensor.3d.shared::cta.global.tile.mbarrier::complete_tx::bytes " \
        "[%0], [%1, {%2, %3, %4}], [%5];" \
        :: "r"((uint32_t)(smem_addr)), "l"(tmap_ptr), \
           "r"((int32_t)(c0)), "r"((int32_t)(c1)), "r"((int32_t)(c2)), \
           "r"((uint32_t)(mbar)) : "memory")

// ---------------------------------------------------------------------------
// Kernel 1: merged prep, grid (32, 32, 3), 256 threads.
//   z==0: x -> fp16 + pooled partials; publishes completion via g_prep_done.
//   z==1 (g<512): streaming convert W1 f32 -> fp16.  (W2 moved to GEMM1 grid)
//   z==2 (y==0, x<32): router for batch x, gated on all z==0 blocks done.
// ---------------------------------------------------------------------------
__global__ __launch_bounds__(256)
void prep_kernel(const float* __restrict__ x,
                 __half* __restrict__ xh,
                 float* __restrict__ pool_part,
                 const float* __restrict__ W1,
                 __half* __restrict__ W1h,
                 const float* __restrict__ Wp,
                 const float* __restrict__ bp,
                 float* __restrict__ probs_out,
                 float* __restrict__ chosen_out)
{
    if (blockIdx.z == 0) {
        const int b  = blockIdx.x;
        const int tc = blockIdx.y;
        const int d0 = threadIdx.x * 2;

        float s0 = 0.0f, s1 = 0.0f;
        #pragma unroll 4
        for (int r = 0; r < 16; ++r) {
            const int t = tc * 16 + r;
            const size_t off = ((size_t)b * T_ + t) * D_ + d0;
            const float2 v = *reinterpret_cast<const float2*>(x + off);
            s0 += v.x; s1 += v.y;
            *reinterpret_cast<__half2*>(xh + off) =
                __halves2half2(__float2half_rn(v.x), __float2half_rn(v.y));
        }
        *reinterpret_cast<float2*>(pool_part + ((size_t)b * 32 + tc) * D_ + d0) =
            make_float2(s0, s1);
        __threadfence();
        __syncthreads();
        if (threadIdx.x == 0) atomicAdd(&g_prep_done, 1);
        return;
    }

    if (blockIdx.z == 2) {
        if (blockIdx.y != 0 || blockIdx.x >= B_) return;
        const int b = blockIdx.x;

        if (threadIdx.x == 0) {
            while (*(volatile int*)&g_prep_done < 32 * 32) __nanosleep(100);
        }
        __syncthreads();
        __threadfence();

        __shared__ float pooled[D_];
        __shared__ float logits[E_];
        #pragma unroll
        for (int k = 0; k < 2; ++k) {
            const int d = threadIdx.x + k * 256;
            float s = 0.0f;
            #pragma unroll
            for (int p = 0; p < 32; ++p)
                s += pool_part[((size_t)b * 32 + p) * D_ + d];
            pooled[d] = s * (1.0f / (float)T_);
        }
        __syncthreads();

        const int warp = threadIdx.x >> 5, lane = threadIdx.x & 31;
        {
            float s = 0.0f;
            #pragma unroll
            for (int k = 0; k < 16; ++k) {
                const int dd = lane + k * 32;
                s += pooled[dd] * Wp[dd * E_ + warp];
            }
            #pragma unroll
            for (int off = 16; off > 0; off >>= 1)
                s += __shfl_down_sync(0xffffffffu, s, off);
            if (lane == 0) logits[warp] = s + bp[warp];
        }
        __syncthreads();

        if (threadIdx.x == 0) {
            float m = logits[0]; int arg = 0;
            #pragma unroll
            for (int e = 1; e < E_; ++e)
                if (logits[e] > m) { m = logits[e]; arg = e; }
            float ex[E_], sum = 0.0f;
            #pragma unroll
            for (int e = 0; e < E_; ++e) { ex[e] = expf(logits[e] - m); sum += ex[e]; }
            const float inv = 1.0f / sum;
            if (probs_out) {
                #pragma unroll
                for (int e = 0; e < E_; ++e) probs_out[b * E_ + e] = ex[e] * inv;
            }
            if (chosen_out) chosen_out[b] = (float)arg;
            g_chosen[b] = arg;
        }
        return;
    }

    // ---- z==1: streaming W1 convert (first 512 blocks only) ----
    {
        const int g = blockIdx.y * 32 + blockIdx.x;
        if (g >= 512) return;
        const float* src = W1 + (size_t)g * 16384;
        __half* dst = W1h + (size_t)g * 16384;
        #pragma unroll
        for (int i = 0; i < 16; ++i) {
            const int idx = (threadIdx.x + i * 256) * 4;
            const float4 v = *reinterpret_cast<const float4*>(src + idx);
            __half2 h0 = __halves2half2(__float2half_rn(v.x), __float2half_rn(v.y));
            __half2 h1 = __halves2half2(__float2half_rn(v.z), __float2half_rn(v.w));
            uint2 pk;
            pk.x = *reinterpret_cast<uint32_t*>(&h0);
            pk.y = *reinterpret_cast<uint32_t*>(&h1);
            *reinterpret_cast<uint2*>(dst + idx) = pk;
        }
    }
}

// ---------------------------------------------------------------------------
// Kernel 2: batched expert GEMM with TMA operand loads.
//   G1: grid (16, 4, 36). z<4 -> W2 streaming convert (256 early blocks,
//       lowest bids, run FIRST overlapping the tensor-bound GEMM body).
//       z>=4 -> GEMM for batch b = z-4.
//   G2: grid (4, 4, 32), plain GEMM, b = z.
// GEMM: CTA tile 128x128, 8 warps of 64x32, BK=64, 3-stage TMA+mbarrier,
// 2 CTA/SM.
// ---------------------------------------------------------------------------
#define STAGE_BYTES 32768
#define MBAR_OFF    (3 * STAGE_BYTES)
#define GEMM_SMEM   (MBAR_OFF + 128)

template <bool G1>   // true: relu + fp16 out; false: f32 out
__global__ __launch_bounds__(256, 2)
void moe_gemm_kernel(const __grid_constant__ CUtensorMap tmA,
                     const __grid_constant__ CUtensorMap tmB,
                     const float* __restrict__ biasAll,
                     float* __restrict__ outF,
                     __half* __restrict__ outH,
                     int K, int Nt,
                     const float* __restrict__ W2src,
                     __half* __restrict__ W2h)
{
    extern __shared__ char smem[];

    int b = blockIdx.z;
    if (G1) {
        if (blockIdx.z < 4) {
            // ---- W2 streaming convert: 256 blocks x 32768 f32 ----
            const int g = blockIdx.z * 64 + blockIdx.y * 16 + blockIdx.x;  // 0..255
            const float* src = W2src + (size_t)g * 32768;
            __half* dst = W2h + (size_t)g * 32768;
            #pragma unroll
            for (int i = 0; i < 32; ++i) {
                const int idx = (threadIdx.x + i * 256) * 4;
                const float4 v = *reinterpret_cast<const float4*>(src + idx);
                __half2 h0 = __halves2half2(__float2half_rn(v.x), __float2half_rn(v.y));
                __half2 h1 = __halves2half2(__float2half_rn(v.z), __float2half_rn(v.w));
                uint2 pk;
                pk.x = *reinterpret_cast<uint32_t*>(&h0);
                pk.y = *reinterpret_cast<uint32_t*>(&h1);
                *reinterpret_cast<uint2*>(dst + idx) = pk;
            }
            return;
        }
        b = blockIdx.z - 4;
        // graph-replay counter reset (stream-ordered after prep kernel)
        if (blockIdx.x == 0 && blockIdx.y == 0 && b == 0 && threadIdx.x == 0)
            g_prep_done = 0;
    }

    const uint32_t sbase = smem_to_u32(smem);
    const int tid  = threadIdx.x;
    const int lane = tid & 31;
    const int wid  = tid >> 5;
    const int warp_m = wid & 1;          // 2 warps along M (64 each)
    const int warp_n = wid >> 1;         // 4 warps along N (32 each)

    const int e  = g_chosen[b];
    const int m0 = blockIdx.y * 128;
    const int n0 = blockIdx.x * 128;

    // A ldmatrix addressing (128B rows, SW128: c16 ^= row&7)
    const int ltile = lane >> 3;
    const int lr    = lane & 7;
    const uint32_t xr = (uint32_t)lr << 4;
    const uint32_t baseA = (uint32_t)(warp_m * 64 + (ltile & 1) * 8 + lr) * 128u;
    const uint32_t kcA   = (uint32_t)(ltile >> 1) * 16u;

    // B ldmatrix.trans addressing: half = warp_n>>1, 64-row x 128B blocks.
    const uint32_t bOff = 16384u + (uint32_t)(warp_n >> 1) * 8192u;
    const uint32_t rowL = (uint32_t)((ltile & 1) * 8 + lr);
    const uint32_t cb0  = (uint32_t)((warp_n & 1) * 4 + (ltile >> 1));
    const uint32_t addrB0 = bOff + rowL * 128u + ((cb0 ^ (uint32_t)lr) << 4);
    const uint32_t addrB1 = bOff + rowL * 128u + (((cb0 + 2u) ^ (uint32_t)lr) << 4);

    float acc[4][4][4];
    #pragma unroll
    for (int mi = 0; mi < 4; ++mi)
        #pragma unroll
        for (int ni = 0; ni < 4; ++ni)
            #pragma unroll
            for (int i = 0; i < 4; ++i) acc[mi][ni][i] = 0.0f;

    const int KB = K >> 6;
    const uint32_t mbar0 = sbase + MBAR_OFF;

    auto issue_stage = [&](int s, int kb2) {
        const uint32_t stg = sbase + (uint32_t)s * STAGE_BYTES;
        const uint32_t mb  = mbar0 + (uint32_t)s * 8u;
        const int k0 = kb2 << 6;
        MBARRIER_EXPECT_TX(mb, STAGE_BYTES);
        TMA_LOAD_3D(stg,           &tmA, k0,       m0, b, mb);
        TMA_LOAD_3D(stg + 16384u,  &tmB, n0,       k0, e, mb);
        TMA_LOAD_3D(stg + 24576u,  &tmB, n0 + 64,  k0, e, mb);
    };

    if (tid == 0) {
        MBARRIER_INIT(mbar0 + 0, 1);
        MBARRIER_INIT(mbar0 + 8, 1);
        MBARRIER_INIT(mbar0 + 16, 1);
        asm volatile("fence.proxy.async.shared::cta;" ::: "memory");
    }
    __syncthreads();
    if (tid == 0) {
        issue_stage(0, 0);
        issue_stage(1, 1);
    }

    uint32_t af[2][4][4], bf[4][2];

    auto load_af = [&](int buf, uint32_t stg, int kk) {
        const uint32_t kA = ((uint32_t)(kk * 32) + kcA) ^ xr;
        #pragma unroll
        for (int mi = 0; mi < 4; ++mi)
            ldsm4(af[buf][mi], stg + baseA + mi * 2048u + kA);
    };
    auto load_bf = [&](uint32_t stg, int kk) {
        const uint32_t kOff = (uint32_t)kk * 2048u;   // 16 k-rows * 128B
        uint32_t t4[4];
        ldsm4t(t4, stg + kOff + addrB0);
        bf[0][0] = t4[0]; bf[0][1] = t4[1];
        bf[1][0] = t4[2]; bf[1][1] = t4[3];
        ldsm4t(t4, stg + kOff + addrB1);
        bf[2][0] = t4[0]; bf[2][1] = t4[1];
        bf[3][0] = t4[2]; bf[3][1] = t4[3];
    };

    for (int kb = 0; kb < KB; ++kb) {
        const int s = kb % 3;
        const int par = (kb / 3) & 1;
        MBARRIER_WAIT_PARITY(mbar0 + (uint32_t)s * 8u, par);
        if (tid == 0 && kb + 2 < KB) issue_stage((kb + 2) % 3, kb + 2);

        const uint32_t stg = sbase + (uint32_t)s * STAGE_BYTES;

        load_af(0, stg, 0);
        #pragma unroll
        for (int kk = 0; kk < 4; ++kk) {
            load_bf(stg, kk);
            if (kk < 3) load_af((kk + 1) & 1, stg, kk + 1);
            #pragma unroll
            for (int mi = 0; mi < 4; ++mi)
                #pragma unroll
                for (int ni = 0; ni < 4; ++ni)
                    mma16816(acc[mi][ni], af[kk & 1][mi], bf[ni]);
        }
        __syncthreads();   // stage consumed; safe for TMA overwrite next iters
    }

    // ---- epilogue ----
    const int gm = m0 + warp_m * 64;
    const int gncol = n0 + warp_n * 32;
    #pragma unroll
    for (int mi = 0; mi < 4; ++mi) {
        const int row0 = gm + mi * 16 + (lane >> 2);
        #pragma unroll
        for (int ni = 0; ni < 4; ++ni) {
            const int col = gncol + ni * 8 + (lane & 3) * 2;
            const float2 bv = *reinterpret_cast<const float2*>(
                biasAll + (size_t)e * Nt + col);
            float v00 = acc[mi][ni][0] + bv.x;
            float v01 = acc[mi][ni][1] + bv.y;
            float v10 = acc[mi][ni][2] + bv.x;
            float v11 = acc[mi][ni][3] + bv.y;
            const size_t o0 = ((size_t)b * T_ + row0) * Nt + col;
            const size_t o1 = ((size_t)b * T_ + row0 + 8) * Nt + col;
            if (G1) {
                v00 = fmaxf(v00, 0.0f); v01 = fmaxf(v01, 0.0f);
                v10 = fmaxf(v10, 0.0f); v11 = fmaxf(v11, 0.0f);
                *reinterpret_cast<__half2*>(outH + o0) =
                    __halves2half2(__float2half_rn(v00), __float2half_rn(v01));
                *reinterpret_cast<__half2*>(outH + o1) =
                    __halves2half2(__float2half_rn(v10), __float2half_rn(v11));
            } else {
                *reinterpret_cast<float2*>(outF + o0) = make_float2(v00, v01);
                *reinterpret_cast<float2*>(outF + o1) = make_float2(v10, v11);
            }
        }
    }
}

// ---------------------------------------------------------------------------
// Host: tensormap encoding via driver entry point
// ---------------------------------------------------------------------------
typedef CUresult (*EncFn)(CUtensorMap*, CUtensorMapDataType, cuuint32_t, void*,
                          const cuuint64_t*, const cuuint64_t*, const cuuint32_t*,
                          const cuuint32_t*, CUtensorMapInterleave,
                          CUtensorMapSwizzle, CUtensorMapL2promotion,
                          CUtensorMapFloatOOBfill);

static EncFn get_encoder()
{
    void* fn = nullptr;
    cudaDriverEntryPointQueryResult st;
#if CUDART_VERSION >= 12050
    cudaGetDriverEntryPointByVersion("cuTensorMapEncodeTiled", &fn, 12000,
                                     cudaEnableDefault, &st);
#else
    cudaGetDriverEntryPoint("cuTensorMapEncodeTiled", &fn,
                            cudaEnableDefault, &st);
#endif
    return (EncFn)fn;
}

static void make_tmap(EncFn enc, CUtensorMap* tm, void* base,
                      uint64_t d0, uint64_t d1, uint64_t d2,
                      uint32_t box0, uint32_t box1)
{
    cuuint64_t dims[3]    = {d0, d1, d2};
    cuuint64_t strides[2] = {d0 * 2, d0 * d1 * 2};
    cuuint32_t box[3]     = {box0, box1, 1};
    cuuint32_t es[3]      = {1, 1, 1};
    enc(tm, CU_TENSOR_MAP_DATA_TYPE_FLOAT16, 3, base, dims, strides, box, es,
        CU_TENSOR_MAP_INTERLEAVE_NONE, CU_TENSOR_MAP_SWIZZLE_128B,
        CU_TENSOR_MAP_L2_PROMOTION_L2_128B, CU_TENSOR_MAP_FLOAT_OOB_FILL_NONE);
}

// ---------------------------------------------------------------------------
// kernel_launch
// ---------------------------------------------------------------------------
extern "C" void kernel_launch(void* const* d_in, const int* in_sizes, int n_in,
                              void* d_out, int out_size)
{
    const float* x  = (const float*)d_in[0];
    const float* Wp = (const float*)d_in[1];
    const float* bp = (const float*)d_in[2];
    const float* W1 = (const float*)d_in[3];
    const float* b1 = (const float*)d_in[4];
    const float* W2 = (const float*)d_in[5];
    const float* b2 = (const float*)d_in[6];
    float* out = (float*)d_out;

    const long long FINAL_N = (long long)B_ * T_ * D_;
    float* probs_out  = nullptr;
    float* chosen_out = nullptr;
    if ((long long)out_size >= FINAL_N + (long long)B_ * E_)
        probs_out = out + FINAL_N;
    if ((long long)out_size >= FINAL_N + (long long)B_ * E_ + B_)
        chosen_out = out + FINAL_N + (long long)B_ * E_;

    __half *xh, *hh, *w1h, *w2h;
    float* pool_part;
    cudaGetSymbolAddress((void**)&xh, g_x_h);
    cudaGetSymbolAddress((void**)&hh, g_h_h);
    cudaGetSymbolAddress((void**)&w1h, g_W1h);
    cudaGetSymbolAddress((void**)&w2h, g_W2h);
    cudaGetSymbolAddress((void**)&pool_part, g_pool_part);

    EncFn enc = get_encoder();
    CUtensorMap tmA1, tmB1, tmA2, tmB2;
    make_tmap(enc, &tmA1, xh,  512, 512, 32, 64, 128);     // A1: (K,T,B)
    make_tmap(enc, &tmB1, w1h, 2048, 512, 8, 64, 64);      // B1: (N,K,E)
    make_tmap(enc, &tmA2, hh,  2048, 512, 32, 64, 128);    // A2
    make_tmap(enc, &tmB2, w2h, 512, 2048, 8, 64, 64);      // B2

    cudaFuncSetAttribute(moe_gemm_kernel<true>,
                         cudaFuncAttributeMaxDynamicSharedMemorySize, GEMM_SMEM);
    cudaFuncSetAttribute(moe_gemm_kernel<false>,
                         cudaFuncAttributeMaxDynamicSharedMemorySize, GEMM_SMEM);

    // 1) prep: x->fp16 + pool partials (z=0), W1 convert (z=1), router (z=2)
    prep_kernel<<<dim3(32, 32, 3), 256>>>(x, xh, pool_part, W1, w1h,
                                          Wp, bp, probs_out, chosen_out);

    // 2) GEMM1 (+early W2 convert blocks at z<4):
    //    h = relu(x @ W1[e] + b1[e]) : M=512, N=2048, K=512
    moe_gemm_kernel<true><<<dim3(H_ / 128, T_ / 128, B_ + 4), 256, GEMM_SMEM>>>(
        tmA1, tmB1, b1, nullptr, hh, D_, H_, W2, w2h);

    // 3) GEMM2: final = h @ W2[e] + b2[e]   : M=512, N=512, K=2048
    moe_gemm_kernel<false><<<dim3(D_ / 128, T_ / 128, B_), 256, GEMM_SMEM>>>(
        tmA2, tmB2, b2, out, nullptr, H_, D_, nullptr, nullptr);
}